// round 12
// baseline (speedup 1.0000x reference)
#include <cuda_runtime.h>
#include <cuda_fp16.h>
#include <cstdint>

#define BATCH   2048
#define LATD    32
#define HID     256
#define DIM     20
#define TST     512

#define ROWS    32                 // batch rows per CLUSTER
#define CLUSTER 2
#define NCTA    ((BATCH / ROWS) * CLUSTER)   // 128
#define NT      256                // 8 warps per CTA
#define NSLOT   16                 // global column-owner slots (2 CTAs x 8)

#define KS0     18                 // layer0: x-pad (2 ks) + h0 (16 ks)
#define KS1     32                 // layer1: h0_new (16 ks) + h1_old (16 ks)
#define AS      1064               // u16 elements per activation row (pad: conflict-free)
#define ROWB    (AS * 2)           // 2128 bytes per row
#define MTOFF   (16 * ROWB)

// u16 column bases inside an activation row
__device__ __constant__ int H0COL[2] = {32, 288};
__device__ __constant__ int H1COL[2] = {544, 800};

// smem byte offsets
#define OFF_AH   0
#define OFF_AL   (32 * AS * 2)                 // 68096
#define OFF_PT   (OFF_AL + 32 * AS * 2)        // 136192
#define OFF_YB   (OFF_PT + 8 * 32 * 33 * 4)    // 169984
#define OFF_B0   (OFF_YB + 640 * 4)            // 172544
#define OFF_B1   (OFF_B0 + 1024 * 4)           // 176640
#define OFF_ZS   (OFF_B1 + 1024 * 4)           // 180736
#define OFF_BAR  (OFF_ZS + 32 * 32 * 4)        // 184832
#define SMEM_BYTES (OFF_BAR + 32)              // 184864

// ---------------- fragment-major packed fp16 weights ----------------
__device__ uint4 g_W0[NSLOT * KS0 * 4 * 32];
__device__ uint4 g_W1[NSLOT * KS1 * 4 * 32];
__device__ uint4 g_PJ[NSLOT * 2 * 32];

// ---------------- helpers ----------------
__device__ __forceinline__ float sigm(float x) {
    return __fdividef(1.f, 1.f + __expf(-x));
}
__device__ __forceinline__ float tanh_(float x) {
    float e = __expf(2.f * x);
    return 1.f - __fdividef(2.f, e + 1.f);
}
__device__ __forceinline__ void split2h(float x, unsigned short& hi, unsigned short& lo) {
    __half h = __float2half_rn(x);
    hi = __half_as_ushort(h);
    lo = __half_as_ushort(__float2half_rn(x - __half2float(h)));
}
__device__ __forceinline__ uint32_t f16x2(float a, float b) {
    unsigned short ha = __half_as_ushort(__float2half_rn(a));
    unsigned short hb = __half_as_ushort(__float2half_rn(b));
    return (uint32_t)ha | ((uint32_t)hb << 16);
}
__device__ __forceinline__ uint32_t smem_u32(const void* p) {
    uint32_t a;
    asm("{ .reg .u64 t; cvta.to.shared.u64 t, %1; cvt.u32.u64 %0, t; }" : "=r"(a) : "l"(p));
    return a;
}
__device__ __forceinline__ uint32_t mapa_sh(uint32_t addr, uint32_t rank) {
    uint32_t r;
    asm("mapa.shared::cluster.u32 %0, %1, %2;" : "=r"(r) : "r"(addr), "r"(rank));
    return r;
}
__device__ __forceinline__ void st_remote_u32(uint32_t addr, uint32_t v) {
    asm volatile("st.shared::cluster.u32 [%0], %1;" :: "r"(addr), "r"(v) : "memory");
}
__device__ __forceinline__ void cluster_sync_() {
    asm volatile("barrier.cluster.arrive.aligned;" ::: "memory");
    asm volatile("barrier.cluster.wait.aligned;" ::: "memory");
}
__device__ __forceinline__ void mbar_init(uint32_t bar, uint32_t count) {
    asm volatile("mbarrier.init.shared.b64 [%0], %1;" :: "r"(bar), "r"(count) : "memory");
}
// arrive (release, cluster scope) on a REMOTE (peer) barrier
__device__ __forceinline__ void mbar_arrive_remote(uint32_t peer_bar) {
    asm volatile("mbarrier.arrive.release.cluster.shared::cluster.b64 _, [%0];"
                 :: "r"(peer_bar) : "memory");
}
__device__ __forceinline__ void mbar_wait(uint32_t bar, uint32_t parity) {
    uint32_t done = 0;
    while (!done) {
        asm volatile(
            "{\n\t.reg .pred p;\n\t"
            "mbarrier.try_wait.parity.acquire.cluster.shared::cta.b64 p, [%1], %2, 0x989680;\n\t"
            "selp.b32 %0, 1, 0, p;\n\t}"
            : "=r"(done) : "r"(bar), "r"(parity) : "memory");
    }
}
__device__ __forceinline__ void ldsm4(uint32_t& r0, uint32_t& r1, uint32_t& r2, uint32_t& r3,
                                      uint32_t a) {
    asm volatile("ldmatrix.sync.aligned.m8n8.x4.shared.b16 {%0,%1,%2,%3}, [%4];"
                 : "=r"(r0), "=r"(r1), "=r"(r2), "=r"(r3) : "r"(a));
}
__device__ __forceinline__ void mma16816(float* c, uint32_t a0, uint32_t a1, uint32_t a2,
                                         uint32_t a3, uint32_t b0, uint32_t b1) {
    asm volatile(
        "mma.sync.aligned.m16n8k16.row.col.f32.f16.f16.f32 "
        "{%0,%1,%2,%3}, {%4,%5,%6,%7}, {%8,%9}, {%0,%1,%2,%3};"
        : "+f"(c[0]), "+f"(c[1]), "+f"(c[2]), "+f"(c[3])
        : "r"(a0), "r"(a1), "r"(a2), "r"(a3), "r"(b0), "r"(b1));
}

// ---------------- repack accessors (kc = k index within layer K-space) ----------------
__device__ __forceinline__ float W0val(int kc, int n,
                                       const float* w_ih0, const float* w_hh0) {
    int u = n >> 2, g = n & 3, row = g * HID + u;
    if (kc < DIM) return w_ih0[row * DIM + kc];
    if (kc < 32)  return 0.f;
    return w_hh0[row * HID + (kc - 32)];
}
__device__ __forceinline__ float W1val(int kc, int n,
                                       const float* w_ih1, const float* w_hh1) {
    int u = n >> 2, g = n & 3, row = g * HID + u;
    return (kc < HID) ? w_ih1[row * HID + kc] : w_hh1[row * HID + (kc - HID)];
}

__global__ void repack_kernel(const float* __restrict__ w_ih0, const float* __restrict__ w_hh0,
                              const float* __restrict__ w_ih1, const float* __restrict__ w_hh1,
                              const float* __restrict__ w_proj) {
    const int stride = gridDim.x * blockDim.x;
    const int base   = blockIdx.x * blockDim.x + threadIdx.x;

    const int N0 = NSLOT * KS0 * 4 * 32;
    for (int idx = base; idx < N0; idx += stride) {
        int lane = idx & 31, t = idx >> 5;
        int pp = t & 1; t >>= 1;
        int hf = t & 1; t >>= 1;
        int ks = t % KS0, s = t / KS0;
        int na = s * 64 + hf * 32 + pp * 16 + (lane >> 2);
        int nb = na + 8;
        int kc = ks * 16 + (lane & 3) * 2;
        uint4 v;
        v.x = f16x2(W0val(kc,     na, w_ih0, w_hh0), W0val(kc + 1, na, w_ih0, w_hh0));
        v.y = f16x2(W0val(kc + 8, na, w_ih0, w_hh0), W0val(kc + 9, na, w_ih0, w_hh0));
        v.z = f16x2(W0val(kc,     nb, w_ih0, w_hh0), W0val(kc + 1, nb, w_ih0, w_hh0));
        v.w = f16x2(W0val(kc + 8, nb, w_ih0, w_hh0), W0val(kc + 9, nb, w_ih0, w_hh0));
        g_W0[idx] = v;
    }
    const int N1 = NSLOT * KS1 * 4 * 32;
    for (int idx = base; idx < N1; idx += stride) {
        int lane = idx & 31, t = idx >> 5;
        int pp = t & 1; t >>= 1;
        int hf = t & 1; t >>= 1;
        int ks = t % KS1, s = t / KS1;
        int na = s * 64 + hf * 32 + pp * 16 + (lane >> 2);
        int nb = na + 8;
        int kc = ks * 16 + (lane & 3) * 2;
        uint4 v;
        v.x = f16x2(W1val(kc,     na, w_ih1, w_hh1), W1val(kc + 1, na, w_ih1, w_hh1));
        v.y = f16x2(W1val(kc + 8, na, w_ih1, w_hh1), W1val(kc + 9, na, w_ih1, w_hh1));
        v.z = f16x2(W1val(kc,     nb, w_ih1, w_hh1), W1val(kc + 1, nb, w_ih1, w_hh1));
        v.w = f16x2(W1val(kc + 8, nb, w_ih1, w_hh1), W1val(kc + 9, nb, w_ih1, w_hh1));
        g_W1[idx] = v;
    }
    // projection: slot s covers w_proj K-cols [s*16, s*16+16)
    const int NP = NSLOT * 2 * 32;
    for (int idx = base; idx < NP; idx += stride) {
        int lane = idx & 31, t = idx >> 5;
        int pp = t & 1;
        int s  = t >> 1;
        int na = pp * 16 + (lane >> 2);
        int nb = na + 8;
        int k  = s * 16 + (lane & 3) * 2;
        auto PV = [&](int n, int kk) -> float {
            return (n < DIM) ? w_proj[n * HID + kk] : 0.f;
        };
        uint4 v;
        v.x = f16x2(PV(na, k),     PV(na, k + 1));
        v.y = f16x2(PV(na, k + 8), PV(na, k + 9));
        v.z = f16x2(PV(nb, k),     PV(nb, k + 1));
        v.w = f16x2(PV(nb, k + 8), PV(nb, k + 9));
        g_PJ[idx] = v;
    }
}

// ---------------- 2-pass fp16-split MMA over one K segment (4 n-tiles, 2 m-tiles) ----------------
template <int KSTEPS>
__device__ __forceinline__ void mma_seg(uint32_t aHi, uint32_t aLo,
                                        const uint4* __restrict__ wf,
                                        float (&acc)[2][4][4]) {
    uint4 B0 = __ldg(wf), B1 = __ldg(wf + 32);
    #pragma unroll 2
    for (int ks = 0; ks < KSTEPS; ++ks) {
        uint4 B0n, B1n;
        if (ks + 1 < KSTEPS) {
            B0n = __ldg(wf + (size_t)(ks + 1) * 128);
            B1n = __ldg(wf + (size_t)(ks + 1) * 128 + 32);
        }
        uint32_t h0, h1, h2, h3, h4, h5, h6, h7;
        uint32_t l0, l1, l2, l3, l4, l5, l6, l7;
        ldsm4(h0, h1, h2, h3, aHi + ks * 32);
        ldsm4(h4, h5, h6, h7, aHi + MTOFF + ks * 32);
        ldsm4(l0, l1, l2, l3, aLo + ks * 32);
        ldsm4(l4, l5, l6, l7, aLo + MTOFF + ks * 32);
        mma16816(acc[0][0], h0, h1, h2, h3, B0.x, B0.y);
        mma16816(acc[0][0], l0, l1, l2, l3, B0.x, B0.y);
        mma16816(acc[1][0], h4, h5, h6, h7, B0.x, B0.y);
        mma16816(acc[1][0], l4, l5, l6, l7, B0.x, B0.y);
        mma16816(acc[0][1], h0, h1, h2, h3, B0.z, B0.w);
        mma16816(acc[0][1], l0, l1, l2, l3, B0.z, B0.w);
        mma16816(acc[1][1], h4, h5, h6, h7, B0.z, B0.w);
        mma16816(acc[1][1], l4, l5, l6, l7, B0.z, B0.w);
        mma16816(acc[0][2], h0, h1, h2, h3, B1.x, B1.y);
        mma16816(acc[0][2], l0, l1, l2, l3, B1.x, B1.y);
        mma16816(acc[1][2], h4, h5, h6, h7, B1.x, B1.y);
        mma16816(acc[1][2], l4, l5, l6, l7, B1.x, B1.y);
        mma16816(acc[0][3], h0, h1, h2, h3, B1.z, B1.w);
        mma16816(acc[0][3], l0, l1, l2, l3, B1.z, B1.w);
        mma16816(acc[1][3], h4, h5, h6, h7, B1.z, B1.w);
        mma16816(acc[1][3], l4, l5, l6, l7, B1.z, B1.w);
        B0 = B0n;  B1 = B1n;
    }
}

// ---------------- LSTM epilogue ----------------
__device__ __forceinline__ void lstm_epi(float (&acc)[2][4][4], int half, int odd,
                                         float (&cs)[2][8], uint32_t (&hp)[2][8]) {
    #pragma unroll
    for (int mt = 0; mt < 2; ++mt) {
        #pragma unroll
        for (int n = 0; n < 4; ++n) {
            float a0 = acc[mt][n][0], a1 = acc[mt][n][1];
            float a2 = acc[mt][n][2], a3 = acc[mt][n][3];
            float t0 = __shfl_xor_sync(0xffffffffu, a0, 1);
            float t1 = __shfl_xor_sync(0xffffffffu, a1, 1);
            float t2 = __shfl_xor_sync(0xffffffffu, a2, 1);
            float t3 = __shfl_xor_sync(0xffffffffu, a3, 1);
            float gi = odd ? t2 : a0;
            float gf = odd ? t3 : a1;
            float gg = odd ? a2 : t0;
            float go = odd ? a3 : t1;
            int idx = half * 4 + n;
            float c = sigm(gf) * cs[mt][idx] + sigm(gi) * tanh_(gg);
            cs[mt][idx] = c;
            float h = sigm(go) * tanh_(c);
            unsigned short hh, hl;
            split2h(h, hh, hl);
            hp[mt][idx] = (uint32_t)hh | ((uint32_t)hl << 16);
        }
    }
}

// ---------------- packed h write-back (local + remote, u32) ----------------
__device__ __forceinline__ void store_h(uint32_t (&hp)[2][8], int slot, int rbaseA,
                                        int colbase, uint16_t* Ah, uint16_t* Al,
                                        uint32_t pAh, uint32_t pAl, bool packlead) {
    #pragma unroll
    for (int mt = 0; mt < 2; ++mt)
        #pragma unroll
        for (int idx = 0; idx < 8; ++idx) {
            uint32_t oth = __shfl_xor_sync(0xffffffffu, hp[mt][idx], 2);
            if (packlead) {
                uint32_t hi2 = (hp[mt][idx] & 0xffffu) | (oth << 16);
                uint32_t lo2 = (hp[mt][idx] >> 16)     | (oth & 0xffff0000u);
                int u   = slot * 16 + idx * 2;          // even unit
                int row = mt * 16 + rbaseA;
                int col = colbase + u;
                *reinterpret_cast<uint32_t*>(&Ah[row * AS + col]) = hi2;
                *reinterpret_cast<uint32_t*>(&Al[row * AS + col]) = lo2;
                uint32_t off = (uint32_t)(row * AS + col) * 2;
                st_remote_u32(pAh + off, hi2);
                st_remote_u32(pAl + off, lo2);
            }
        }
}

// ---------------- main persistent clustered kernel ----------------
__global__ void __launch_bounds__(NT, 1) __cluster_dims__(CLUSTER, 1, 1)
decoder_kernel(const float* __restrict__ z,
               const float* __restrict__ w_lh, const float* __restrict__ b_lh,
               const float* __restrict__ w_lc, const float* __restrict__ b_lc,
               const float* __restrict__ b_ih0, const float* __restrict__ b_hh0,
               const float* __restrict__ b_ih1, const float* __restrict__ b_hh1,
               const float* __restrict__ b_proj,
               float* __restrict__ out) {
    extern __shared__ __align__(16) char smem[];
    uint16_t* Ah   = (uint16_t*)(smem + OFF_AH);
    uint16_t* Al   = (uint16_t*)(smem + OFF_AL);
    float*    pt   = (float*)(smem + OFF_PT);     // [8][32][33]
    float*    ybuf = (float*)(smem + OFF_YB);     // [640] (peer's partial y)
    float*    b0s  = (float*)(smem + OFF_B0);     // [1024]
    float*    b1s  = (float*)(smem + OFF_B1);     // [1024]
    float*    z_s  = (float*)(smem + OFF_ZS);     // [32][32]

    const int tid  = threadIdx.x;
    const int wid  = tid >> 5;
    const int lane = tid & 31;
    const int tig  = lane & 3;
    const int odd  = lane & 1;
    uint32_t cr;
    asm("mov.u32 %0, %%cluster_ctarank;" : "=r"(cr));
    const uint32_t peer = cr ^ 1u;
    const int slot = (int)cr * 8 + wid;
    const int r0   = (blockIdx.x / CLUSTER) * ROWS;
    const int ubase  = slot * 16 + (tig >> 1);
    const int rbaseA = (lane >> 2) + (odd ? 8 : 0);
    const bool packlead = (lane & 2) == 0;

    const uint32_t smemB = smem_u32(smem);
    const uint32_t barA = smemB + OFF_BAR;
    const uint32_t barB = smemB + OFF_BAR + 8;

    // ---- init: z slab, x zeros, biases, barriers ----
    for (int i = tid; i < ROWS * LATD; i += NT) z_s[i] = z[(size_t)r0 * LATD + i];
    for (int i = tid; i < 32 * 32; i += NT) {
        int r = i >> 5, c = i & 31;
        Ah[r * AS + c] = 0;
        Al[r * AS + c] = 0;
    }
    for (int i = tid; i < 1024; i += NT) {
        int u = i >> 2, g = i & 3;
        b0s[i] = b_ih0[g * HID + u] + b_hh0[g * HID + u];
        b1s[i] = b_ih1[g * HID + u] + b_hh1[g * HID + u];
    }
    if (tid == 0) { mbar_init(barA, NT); mbar_init(barB, NT); }
    __syncthreads();

    // ---- c-state init (own units, both m-tiles) ----
    float c0st[2][8], c1st[2][8];
    #pragma unroll
    for (int nt = 0; nt < 8; ++nt) {
        int u = ubase + nt * 2;
        float s00 = b_lc[u], s01 = b_lc[HID + u];
        float s10 = s00,     s11 = s01;
        for (int k = 0; k < LATD; ++k) {
            float wa = __ldg(w_lc + (size_t)u * LATD + k);
            float wb = __ldg(w_lc + (size_t)(HID + u) * LATD + k);
            float z0 = z_s[rbaseA * LATD + k];
            float z1 = z_s[(16 + rbaseA) * LATD + k];
            s00 = fmaf(z0, wa, s00);  s01 = fmaf(z0, wb, s01);
            s10 = fmaf(z1, wa, s10);  s11 = fmaf(z1, wb, s11);
        }
        c0st[0][nt] = s00;  c1st[0][nt] = s01;
        c0st[1][nt] = s10;  c1st[1][nt] = s11;
    }

    // ---- h-state init into buffer 0 (full A filled by each CTA; init-only) ----
    {
        int u2 = tid;                                // 0..255
        for (int rb = 0; rb < 32; rb += 16) {
            float h0v[16], h1v[16];
            #pragma unroll
            for (int r = 0; r < 16; ++r) { h0v[r] = b_lh[u2]; h1v[r] = b_lh[HID + u2]; }
            for (int k = 0; k < LATD; ++k) {
                float wa = __ldg(w_lh + (size_t)u2 * LATD + k);
                float wb = __ldg(w_lh + (size_t)(HID + u2) * LATD + k);
                #pragma unroll
                for (int r = 0; r < 16; ++r) {
                    float zv = z_s[(rb + r) * LATD + k];
                    h0v[r] = fmaf(zv, wa, h0v[r]);
                    h1v[r] = fmaf(zv, wb, h1v[r]);
                }
            }
            #pragma unroll
            for (int r = 0; r < 16; ++r) {
                unsigned short hh, hl;
                split2h(h0v[r], hh, hl);
                Ah[(rb + r) * AS + H0COL[0] + u2] = hh;
                Al[(rb + r) * AS + H0COL[0] + u2] = hl;
                split2h(h1v[r], hh, hl);
                Ah[(rb + r) * AS + H1COL[0] + u2] = hh;
                Al[(rb + r) * AS + H1COL[0] + u2] = hl;
            }
        }
    }
    __syncthreads();
    cluster_sync_();   // mbarriers + A planes ready cluster-wide

    const uint32_t AhB = smemB + OFF_AH;
    const uint32_t AlB = smemB + OFF_AL;
    const uint32_t pAh  = mapa_sh(AhB, peer);
    const uint32_t pAl  = mapa_sh(AlB, peer);
    const uint32_t pY   = mapa_sh(smemB + OFF_YB, peer);
    const uint32_t pBarA = mapa_sh(barA, peer);
    const uint32_t pBarB = mapa_sh(barB, peer);
    const uint32_t aH = AhB + (lane & 15) * ROWB + (lane >> 4) * 16;
    const uint32_t aL = AlB + (lane & 15) * ROWB + (lane >> 4) * 16;
    const uint4* wf0 = g_W0 + (size_t)slot * KS0 * 128 + lane;
    const uint4* wf1 = g_W1 + (size_t)slot * KS1 * 128 + lane;
    const uint4* wfP = g_PJ + (size_t)slot * 64 + lane;

    // =============================== time loop ===============================
    for (int t = 0; t < TST; ++t) {
        const uint32_t p = (uint32_t)t & 1u;
        const uint32_t h0rB = (uint32_t)H0COL[p] * 2, h0wB = (uint32_t)H0COL[p ^ 1] * 2;
        const uint32_t h1rB = (uint32_t)H1COL[p] * 2, h1wB = (uint32_t)H1COL[p ^ 1] * 2;
        uint32_t hp[2][8];

        // ---- layer 0 : x (2 ks) + h0_old (16 ks) ----
        #pragma unroll
        for (int half = 0; half < 2; ++half) {
            float acc[2][4][4];
            #pragma unroll
            for (int j = 0; j < 4; ++j) {
                const float* bp = b0s + slot * 64 + half * 32 + j * 8 + 2 * tig;
                float bx = bp[0], by = bp[1];
                acc[0][j][0] = bx; acc[0][j][1] = by; acc[0][j][2] = bx; acc[0][j][3] = by;
                acc[1][j][0] = bx; acc[1][j][1] = by; acc[1][j][2] = bx; acc[1][j][3] = by;
            }
            mma_seg<2>(aH, aL, wf0 + half * 64, acc);
            mma_seg<16>(aH + h0rB, aL + h0rB, wf0 + 2 * 128 + half * 64, acc);
            lstm_epi(acc, half, odd, c0st, hp);
        }
        store_h(hp, slot, rbaseA, H0COL[p ^ 1], Ah, Al, pAh, pAl, packlead);
        mbar_arrive_remote(pBarA);                   // each thread: releases its own stores
        __syncthreads();                             // local visibility of h0_new
        mbar_wait(barA, p);                          // peer's h0_new arrived

        // ---- layer 1 : h0_new (16 ks) + h1_old (16 ks) ----
        #pragma unroll
        for (int half = 0; half < 2; ++half) {
            float acc[2][4][4];
            #pragma unroll
            for (int j = 0; j < 4; ++j) {
                const float* bp = b1s + slot * 64 + half * 32 + j * 8 + 2 * tig;
                float bx = bp[0], by = bp[1];
                acc[0][j][0] = bx; acc[0][j][1] = by; acc[0][j][2] = bx; acc[0][j][3] = by;
                acc[1][j][0] = bx; acc[1][j][1] = by; acc[1][j][2] = bx; acc[1][j][3] = by;
            }
            mma_seg<16>(aH + h0wB, aL + h0wB, wf1 + half * 64, acc);
            mma_seg<16>(aH + h1rB, aL + h1rB, wf1 + 16 * 128 + half * 64, acc);
            lstm_epi(acc, half, odd, c1st, hp);
        }
        store_h(hp, slot, rbaseA, H1COL[p ^ 1], Ah, Al, pAh, pAl, packlead);
        __syncwarp();                                // own warp's h1 cols visible to itself

        // ---- projection: LOCAL own 128 units only (warp wid reads its own 16 cols) ----
        {
            float pac[2][4][4];
            #pragma unroll
            for (int mt = 0; mt < 2; ++mt)
                #pragma unroll
                for (int n = 0; n < 4; ++n)
                    #pragma unroll
                    for (int i = 0; i < 4; ++i) pac[mt][n][i] = 0.f;
            uint32_t aPH = aH + h1wB + (uint32_t)(cr * 128 + wid * 16) * 2;
            uint32_t aPL = aL + h1wB + (uint32_t)(cr * 128 + wid * 16) * 2;
            uint4 B0 = __ldg(wfP), B1 = __ldg(wfP + 32);
            #pragma unroll
            for (int mt = 0; mt < 2; ++mt) {
                uint32_t h0r, h1r, h2r, h3r, l0r, l1r, l2r, l3r;
                ldsm4(h0r, h1r, h2r, h3r, aPH + mt * MTOFF);
                ldsm4(l0r, l1r, l2r, l3r, aPL + mt * MTOFF);
                mma16816(pac[mt][0], h0r, h1r, h2r, h3r, B0.x, B0.y);
                mma16816(pac[mt][0], l0r, l1r, l2r, l3r, B0.x, B0.y);
                mma16816(pac[mt][1], h0r, h1r, h2r, h3r, B0.z, B0.w);
                mma16816(pac[mt][1], l0r, l1r, l2r, l3r, B0.z, B0.w);
                mma16816(pac[mt][2], h0r, h1r, h2r, h3r, B1.x, B1.y);
                mma16816(pac[mt][2], l0r, l1r, l2r, l3r, B1.x, B1.y);
                mma16816(pac[mt][3], h0r, h1r, h2r, h3r, B1.z, B1.w);
                mma16816(pac[mt][3], l0r, l1r, l2r, l3r, B1.z, B1.w);
            }
            #pragma unroll
            for (int mt = 0; mt < 2; ++mt)
                #pragma unroll
                for (int n = 0; n < 4; ++n) {
                    int rr = mt * 16 + (lane >> 2);
                    float* pp = pt + wid * 1056 + rr * 33 + n * 8 + tig * 2;
                    pp[0]          = pac[mt][n][0];
                    pp[1]          = pac[mt][n][1];
                    pp[8 * 33]     = pac[mt][n][2];
                    pp[8 * 33 + 1] = pac[mt][n][3];
                }
        }
        __syncthreads();                             // partials visible

        // ---- own-unit partial y; send to peer; handshake B ----
        float ysav[3];
        {
            int nv = 0;
            for (int o = tid; o < ROWS * DIM; o += NT) {
                int r = o / DIM, d = o - r * DIM;
                float s = 0.f;
                #pragma unroll
                for (int w8 = 0; w8 < 8; ++w8) s += pt[w8 * 1056 + r * 33 + d];
                ysav[nv++] = s;
                st_remote_u32(pY + (uint32_t)o * 4, __float_as_uint(s));
            }
        }
        mbar_arrive_remote(pBarB);                   // releases h1 stores + y partials
        mbar_wait(barB, p);

        // ---- final y = own + peer + bias; write out; feed back x ----
        {
            int nv = 0;
            for (int o = tid; o < ROWS * DIM; o += NT) {
                int r = o / DIM, d = o - r * DIM;
                float y = ysav[nv++] + ybuf[o] + __ldg(b_proj + d);
                if ((uint32_t)(r >> 4) == cr)
                    out[(size_t)(r0 + r) * (TST * DIM) + (size_t)t * DIM + d] = y;
                unsigned short hh, hl;
                split2h(y, hh, hl);
                Ah[r * AS + d] = hh;
                Al[r * AS + d] = hl;
            }
        }
        __syncthreads();                             // x visible for next layer0
    }
    cluster_sync_();
}

extern "C" void kernel_launch(void* const* d_in, const int* in_sizes, int n_in,
                              void* d_out, int out_size) {
    const int wbase = (n_in >= 17) ? 3 : 2;

    const float* z      = (const float*)d_in[0];
    const float* w_lh   = (const float*)d_in[wbase + 0];
    const float* b_lh   = (const float*)d_in[wbase + 1];
    const float* w_lc   = (const float*)d_in[wbase + 2];
    const float* b_lc   = (const float*)d_in[wbase + 3];
    const float* w_ih0  = (const float*)d_in[wbase + 4];
    const float* w_hh0  = (const float*)d_in[wbase + 5];
    const float* b_ih0  = (const float*)d_in[wbase + 6];
    const float* b_hh0  = (const float*)d_in[wbase + 7];
    const float* w_ih1  = (const float*)d_in[wbase + 8];
    const float* w_hh1  = (const float*)d_in[wbase + 9];
    const float* b_ih1  = (const float*)d_in[wbase + 10];
    const float* b_hh1  = (const float*)d_in[wbase + 11];
    const float* w_proj = (const float*)d_in[wbase + 12];
    const float* b_proj = (const float*)d_in[wbase + 13];

    static bool attr_set = false;
    if (!attr_set) {
        cudaFuncSetAttribute(decoder_kernel,
                             cudaFuncAttributeMaxDynamicSharedMemorySize, SMEM_BYTES);
        attr_set = true;
    }

    repack_kernel<<<512, 256>>>(w_ih0, w_hh0, w_ih1, w_hh1, w_proj);
    decoder_kernel<<<NCTA, NT, SMEM_BYTES>>>(z, w_lh, b_lh, w_lc, b_lc,
                                             b_ih0, b_hh0, b_ih1, b_hh1,
                                             b_proj, (float*)d_out);
}

// round 13
// speedup vs baseline: 1.3097x; 1.3097x over previous
#include <cuda_runtime.h>
#include <cuda_fp16.h>
#include <cstdint>

#define BATCH   2048
#define LATD    32
#define HID     256
#define DIM     20
#define TST     512

#define ROWS    32                 // batch rows per CLUSTER
#define CLUSTER 2
#define NCTA    ((BATCH / ROWS) * CLUSTER)   // 128
#define NT      256                // 8 warps per CTA
#define NWCTA   8
#define NSLOT   16                 // global column-owner slots (2 CTAs x 8)

#define KS0     18                 // layer0: cols 0..287  (x|1|0|h0)
#define KS1     33                 // layer1: cols 16..543 (..|1|..|h0|h1)
#define AS      552                // u16 elements per activation row
#define ROWB    (AS * 2)           // bytes per row
#define MTOFF   (16 * ROWB)        // m-tile 1 byte offset
#define H0C     32
#define H1C     288

#define SMEM_BYTES (32*AS*2 + 8*32*33*4 + ROWS*LATD*4)   // 73216

// ---------------- fragment-major packed fp16 weights (repacked each launch) ----------------
// gates layout: [slot][ks][half(2)][pp(2)][lane]  (uint4 = 2 n-tiles x {b0,b1})
__device__ uint4 g_W0[NSLOT * KS0 * 4 * 32];
__device__ uint4 g_W1[NSLOT * KS1 * 4 * 32];
__device__ uint4 g_PJ[8 * 2 * 2 * 32];      // [pk][ks][pp][lane]

// ---------------- helpers ----------------
__device__ __forceinline__ float sigm(float x) {
    return __fdividef(1.f, 1.f + __expf(-x));
}
__device__ __forceinline__ float tanh_(float x) {
    float e = __expf(2.f * x);
    return 1.f - __fdividef(2.f, e + 1.f);
}
__device__ __forceinline__ unsigned short f16u(float x) {
    return __half_as_ushort(__float2half_rn(x));
}
__device__ __forceinline__ uint32_t f16x2(float a, float b) {
    return (uint32_t)f16u(a) | ((uint32_t)f16u(b) << 16);
}
__device__ __forceinline__ uint32_t smem_u32(const void* p) {
    uint32_t a;
    asm("{ .reg .u64 t; cvta.to.shared.u64 t, %1; cvt.u32.u64 %0, t; }" : "=r"(a) : "l"(p));
    return a;
}
__device__ __forceinline__ uint32_t mapa_sh(uint32_t addr, uint32_t rank) {
    uint32_t r;
    asm("mapa.shared::cluster.u32 %0, %1, %2;" : "=r"(r) : "r"(addr), "r"(rank));
    return r;
}
__device__ __forceinline__ void st_remote_u32(uint32_t addr, uint32_t v) {
    asm volatile("st.shared::cluster.u32 [%0], %1;" :: "r"(addr), "r"(v) : "memory");
}
__device__ __forceinline__ void cluster_sync_() {
    asm volatile("barrier.cluster.arrive.aligned;" ::: "memory");
    asm volatile("barrier.cluster.wait.aligned;" ::: "memory");
}
__device__ __forceinline__ void ldsm4(uint32_t& r0, uint32_t& r1, uint32_t& r2, uint32_t& r3,
                                      uint32_t a) {
    asm volatile("ldmatrix.sync.aligned.m8n8.x4.shared.b16 {%0,%1,%2,%3}, [%4];"
                 : "=r"(r0), "=r"(r1), "=r"(r2), "=r"(r3) : "r"(a));
}
__device__ __forceinline__ void mma16816(float* c, uint32_t a0, uint32_t a1, uint32_t a2,
                                         uint32_t a3, uint32_t b0, uint32_t b1) {
    asm volatile(
        "mma.sync.aligned.m16n8k16.row.col.f32.f16.f16.f32 "
        "{%0,%1,%2,%3}, {%4,%5,%6,%7}, {%8,%9}, {%0,%1,%2,%3};"
        : "+f"(c[0]), "+f"(c[1]), "+f"(c[2]), "+f"(c[3])
        : "r"(a0), "r"(a1), "r"(a2), "r"(a3), "r"(b0), "r"(b1));
}

// ---------------- repack: weight element accessors (kc = activation column) ----------------
__device__ __forceinline__ float W0val(int kc, int n,
                                       const float* w_ih0, const float* w_hh0,
                                       const float* b_ih0, const float* b_hh0) {
    int u = n >> 2, g = n & 3, row = g * HID + u;
    if (kc < DIM)  return w_ih0[row * DIM + kc];
    if (kc == 20)  return b_ih0[row] + b_hh0[row];
    if (kc < 32)   return 0.f;
    return w_hh0[row * HID + (kc - 32)];
}
__device__ __forceinline__ float W1val(int kc, int n,
                                       const float* w_ih1, const float* w_hh1,
                                       const float* b_ih1, const float* b_hh1) {
    int u = n >> 2, g = n & 3, row = g * HID + u;
    if (kc == 20)  return b_ih1[row] + b_hh1[row];
    if (kc >= 288) return w_hh1[row * HID + (kc - 288)];
    if (kc >= 32)  return w_ih1[row * HID + (kc - 32)];
    return 0.f;
}

__global__ void repack_kernel(const float* __restrict__ w_ih0, const float* __restrict__ w_hh0,
                              const float* __restrict__ b_ih0, const float* __restrict__ b_hh0,
                              const float* __restrict__ w_ih1, const float* __restrict__ w_hh1,
                              const float* __restrict__ b_ih1, const float* __restrict__ b_hh1,
                              const float* __restrict__ w_proj) {
    const int stride = gridDim.x * blockDim.x;
    const int base   = blockIdx.x * blockDim.x + threadIdx.x;

    const int N0 = NSLOT * KS0 * 4 * 32;
    for (int idx = base; idx < N0; idx += stride) {
        int lane = idx & 31, t = idx >> 5;
        int pp = t & 1; t >>= 1;
        int hf = t & 1; t >>= 1;
        int ks = t % KS0, s = t / KS0;
        int na = s * 64 + hf * 32 + pp * 16 + (lane >> 2);
        int nb = na + 8;
        int kc = ks * 16 + (lane & 3) * 2;
        uint4 v;
        v.x = f16x2(W0val(kc,     na, w_ih0, w_hh0, b_ih0, b_hh0),
                    W0val(kc + 1, na, w_ih0, w_hh0, b_ih0, b_hh0));
        v.y = f16x2(W0val(kc + 8, na, w_ih0, w_hh0, b_ih0, b_hh0),
                    W0val(kc + 9, na, w_ih0, w_hh0, b_ih0, b_hh0));
        v.z = f16x2(W0val(kc,     nb, w_ih0, w_hh0, b_ih0, b_hh0),
                    W0val(kc + 1, nb, w_ih0, w_hh0, b_ih0, b_hh0));
        v.w = f16x2(W0val(kc + 8, nb, w_ih0, w_hh0, b_ih0, b_hh0),
                    W0val(kc + 9, nb, w_ih0, w_hh0, b_ih0, b_hh0));
        g_W0[idx] = v;
    }
    const int N1 = NSLOT * KS1 * 4 * 32;
    for (int idx = base; idx < N1; idx += stride) {
        int lane = idx & 31, t = idx >> 5;
        int pp = t & 1; t >>= 1;
        int hf = t & 1; t >>= 1;
        int ks = t % KS1, s = t / KS1;
        int na = s * 64 + hf * 32 + pp * 16 + (lane >> 2);
        int nb = na + 8;
        int kc = 16 + ks * 16 + (lane & 3) * 2;
        uint4 v;
        v.x = f16x2(W1val(kc,     na, w_ih1, w_hh1, b_ih1, b_hh1),
                    W1val(kc + 1, na, w_ih1, w_hh1, b_ih1, b_hh1));
        v.y = f16x2(W1val(kc + 8, na, w_ih1, w_hh1, b_ih1, b_hh1),
                    W1val(kc + 9, na, w_ih1, w_hh1, b_ih1, b_hh1));
        v.z = f16x2(W1val(kc,     nb, w_ih1, w_hh1, b_ih1, b_hh1),
                    W1val(kc + 1, nb, w_ih1, w_hh1, b_ih1, b_hh1));
        v.w = f16x2(W1val(kc + 8, nb, w_ih1, w_hh1, b_ih1, b_hh1),
                    W1val(kc + 9, nb, w_ih1, w_hh1, b_ih1, b_hh1));
        g_W1[idx] = v;
    }
    const int NP = 8 * 2 * 2 * 32;
    for (int idx = base; idx < NP; idx += stride) {
        int lane = idx & 31, t = idx >> 5;
        int pp = t & 1; t >>= 1;
        int ks = t & 1; t >>= 1;
        int w  = t;                                   // 0..7
        int na = pp * 16 + (lane >> 2);
        int nb = na + 8;
        int kc = w * 32 + ks * 16 + (lane & 3) * 2;
        auto PV = [&](int n, int k) -> float {
            return (n < DIM) ? w_proj[n * HID + k] : 0.f;
        };
        uint4 v;
        v.x = f16x2(PV(na, kc),     PV(na, kc + 1));
        v.y = f16x2(PV(na, kc + 8), PV(na, kc + 9));
        v.z = f16x2(PV(nb, kc),     PV(nb, kc + 1));
        v.w = f16x2(PV(nb, kc + 8), PV(nb, kc + 9));
        g_PJ[idx] = v;
    }
}

// ---------------- single-pass fp16 MMA over one half (4 n-tiles, 2 m-tiles) ----------------
template <int KSTEPS, int KSTRIDE>
__device__ __forceinline__ void mma_half(uint32_t aHi,
                                         const uint4* __restrict__ wf,
                                         float (&acc)[2][4][4]) {
    #pragma unroll
    for (int mt = 0; mt < 2; ++mt)
        #pragma unroll
        for (int n = 0; n < 4; ++n)
            #pragma unroll
            for (int i = 0; i < 4; ++i) acc[mt][n][i] = 0.f;

    uint4 B0 = __ldg(wf), B1 = __ldg(wf + 32);

    #pragma unroll 2
    for (int ks = 0; ks < KSTEPS; ++ks) {
        uint4 B0n, B1n;
        if (ks + 1 < KSTEPS) {
            B0n = __ldg(wf + (size_t)(ks + 1) * KSTRIDE);
            B1n = __ldg(wf + (size_t)(ks + 1) * KSTRIDE + 32);
        }
        uint32_t h0, h1, h2, h3, h4, h5, h6, h7;
        ldsm4(h0, h1, h2, h3, aHi + ks * 32);
        ldsm4(h4, h5, h6, h7, aHi + MTOFF + ks * 32);
        mma16816(acc[0][0], h0, h1, h2, h3, B0.x, B0.y);
        mma16816(acc[1][0], h4, h5, h6, h7, B0.x, B0.y);
        mma16816(acc[0][1], h0, h1, h2, h3, B0.z, B0.w);
        mma16816(acc[1][1], h4, h5, h6, h7, B0.z, B0.w);
        mma16816(acc[0][2], h0, h1, h2, h3, B1.x, B1.y);
        mma16816(acc[1][2], h4, h5, h6, h7, B1.x, B1.y);
        mma16816(acc[0][3], h0, h1, h2, h3, B1.z, B1.w);
        mma16816(acc[1][3], h4, h5, h6, h7, B1.z, B1.w);
        B0 = B0n;  B1 = B1n;
    }
}

// ---------------- LSTM epilogue: gate regroup via lane-pair shuffle ----------------
__device__ __forceinline__ void lstm_epi(float (&acc)[2][4][4], int half, int odd,
                                         float (&cs)[2][8], uint32_t (&hp)[2][8]) {
    #pragma unroll
    for (int mt = 0; mt < 2; ++mt) {
        #pragma unroll
        for (int n = 0; n < 4; ++n) {
            float a0 = acc[mt][n][0], a1 = acc[mt][n][1];
            float a2 = acc[mt][n][2], a3 = acc[mt][n][3];
            float t0 = __shfl_xor_sync(0xffffffffu, a0, 1);
            float t1 = __shfl_xor_sync(0xffffffffu, a1, 1);
            float t2 = __shfl_xor_sync(0xffffffffu, a2, 1);
            float t3 = __shfl_xor_sync(0xffffffffu, a3, 1);
            float gi = odd ? t2 : a0;
            float gf = odd ? t3 : a1;
            float gg = odd ? a2 : t0;
            float go = odd ? a3 : t1;
            int idx = half * 4 + n;
            float c = sigm(gf) * cs[mt][idx] + sigm(gi) * tanh_(gg);
            cs[mt][idx] = c;
            float h = sigm(go) * tanh_(c);
            hp[mt][idx] = (uint32_t)f16u(h);
        }
    }
}

// ---------------- main persistent clustered kernel ----------------
__global__ void __launch_bounds__(NT, 1) __cluster_dims__(CLUSTER, 1, 1)
decoder_kernel(const float* __restrict__ z,
               const float* __restrict__ w_lh, const float* __restrict__ b_lh,
               const float* __restrict__ w_lc, const float* __restrict__ b_lc,
               const float* __restrict__ b_proj,
               float* __restrict__ out) {
    extern __shared__ __align__(16) char smem[];
    uint16_t* Ah  = (uint16_t*)smem;                 // [32][AS] fp16 activations
    float*    pt  = (float*)(Ah + 32 * AS);          // [8][32][33] proj partials
    float*    z_s = pt + 8 * 32 * 33;                // [32][32]

    const int tid  = threadIdx.x;
    const int wid  = tid >> 5;
    const int lane = tid & 31;
    const int tig  = lane & 3;
    const int odd  = lane & 1;
    uint32_t cr;
    asm("mov.u32 %0, %%cluster_ctarank;" : "=r"(cr));
    const int slot = (int)cr * NWCTA + wid;          // global column-owner slot
    const int r0   = (blockIdx.x / CLUSTER) * ROWS;
    const int ubase  = slot * 16 + (tig >> 1);
    const int rbaseA = (lane >> 2) + (odd ? 8 : 0);
    const bool packlead = (lane & 2) == 0;           // pairs lanes via xor 2

    // ---- stage z; init x-pad cols 0..31 (col 20 = fp16 1.0 bias column) ----
    for (int i = tid; i < ROWS * LATD; i += NT) z_s[i] = z[(size_t)r0 * LATD + i];
    for (int i = tid; i < 32 * 32; i += NT) {
        int r = i >> 5, c = i & 31;
        Ah[r * AS + c] = (c == 20) ? (uint16_t)0x3C00 : (uint16_t)0;
    }
    __syncthreads();

    // ---- c-state init in C-fragment layout (own units, both m-tiles) ----
    float c0st[2][8], c1st[2][8];
    #pragma unroll
    for (int nt = 0; nt < 8; ++nt) {
        int u = ubase + nt * 2;
        float s00 = b_lc[u], s01 = b_lc[HID + u];
        float s10 = s00,     s11 = s01;
        for (int k = 0; k < LATD; ++k) {
            float wa = __ldg(w_lc + (size_t)u * LATD + k);
            float wb = __ldg(w_lc + (size_t)(HID + u) * LATD + k);
            float z0 = z_s[rbaseA * LATD + k];
            float z1 = z_s[(16 + rbaseA) * LATD + k];
            s00 = fmaf(z0, wa, s00);  s01 = fmaf(z0, wb, s01);
            s10 = fmaf(z1, wa, s10);  s11 = fmaf(z1, wb, s11);
        }
        c0st[0][nt] = s00;  c1st[0][nt] = s01;
        c0st[1][nt] = s10;  c1st[1][nt] = s11;
    }

    // ---- h-state init into Ah: each CTA fills the FULL A (redundant, init-only) ----
    {
        int u2 = tid;                                // 0..255
        for (int rb = 0; rb < 32; rb += 16) {
            float h0v[16], h1v[16];
            #pragma unroll
            for (int r = 0; r < 16; ++r) { h0v[r] = b_lh[u2]; h1v[r] = b_lh[HID + u2]; }
            for (int k = 0; k < LATD; ++k) {
                float wa = __ldg(w_lh + (size_t)u2 * LATD + k);
                float wb = __ldg(w_lh + (size_t)(HID + u2) * LATD + k);
                #pragma unroll
                for (int r = 0; r < 16; ++r) {
                    float zv = z_s[(rb + r) * LATD + k];
                    h0v[r] = fmaf(zv, wa, h0v[r]);
                    h1v[r] = fmaf(zv, wb, h1v[r]);
                }
            }
            #pragma unroll
            for (int r = 0; r < 16; ++r) {
                Ah[(rb + r) * AS + H0C + u2] = f16u(h0v[r]);
                Ah[(rb + r) * AS + H1C + u2] = f16u(h1v[r]);
            }
        }
    }
    __syncthreads();

    const uint32_t AhB = smem_u32(Ah);
    const uint32_t pAh = mapa_sh(AhB, cr ^ 1u);
    const uint32_t aH = AhB + (lane & 15) * ROWB + (lane >> 4) * 16;
    const uint4* wf0 = g_W0 + (size_t)slot * KS0 * 128 + lane;
    const uint4* wf1 = g_W1 + (size_t)slot * KS1 * 128 + lane;
    const uint4* wfP = g_PJ + (size_t)wid * 128 + lane;

    cluster_sync_();

    // =============================== time loop ===============================
    for (int t = 0; t < TST; ++t) {
        uint32_t hp[2][8];

        // ---- layer 0 : reads cols 0..287 ----
        #pragma unroll
        for (int half = 0; half < 2; ++half) {
            float acc[2][4][4];
            mma_half<KS0, 128>(aH, wf0 + half * 64, acc);
            lstm_epi(acc, half, odd, c0st, hp);
        }
        cluster_sync_();                              // both CTAs done reading h0_old
        #pragma unroll
        for (int mt = 0; mt < 2; ++mt)
            #pragma unroll
            for (int nt = 0; nt < 8; ++nt) {
                uint32_t oth = __shfl_xor_sync(0xffffffffu, hp[mt][nt], 2);
                if (packlead) {
                    uint32_t v = (hp[mt][nt] & 0xffffu) | (oth << 16);
                    int row = mt * 16 + rbaseA, u = ubase + nt * 2;   // u even
                    uint32_t off = (uint32_t)(row * AS + H0C + u) * 2;
                    *reinterpret_cast<uint32_t*>(&Ah[row * AS + H0C + u]) = v;
                    st_remote_u32(pAh + off, v);
                }
            }
        cluster_sync_();                              // new h0 visible cluster-wide

        // ---- layer 1 : reads cols 16..543 ----
        #pragma unroll
        for (int half = 0; half < 2; ++half) {
            float acc[2][4][4];
            mma_half<KS1, 128>(aH + 32, wf1 + half * 64, acc);
            lstm_epi(acc, half, odd, c1st, hp);
        }
        cluster_sync_();                              // both CTAs done reading h1_old
        #pragma unroll
        for (int mt = 0; mt < 2; ++mt)
            #pragma unroll
            for (int nt = 0; nt < 8; ++nt) {
                uint32_t oth = __shfl_xor_sync(0xffffffffu, hp[mt][nt], 2);
                if (packlead) {
                    uint32_t v = (hp[mt][nt] & 0xffffu) | (oth << 16);
                    int row = mt * 16 + rbaseA, u = ubase + nt * 2;
                    uint32_t off = (uint32_t)(row * AS + H1C + u) * 2;
                    *reinterpret_cast<uint32_t*>(&Ah[row * AS + H1C + u]) = v;
                    st_remote_u32(pAh + off, v);
                }
            }
        cluster_sync_();                              // new h1 visible cluster-wide

        // ---- projection MMA: 8 warps K-split (K=32 each), partials -> SMEM ----
        {
            float acc[2][4][4];
            mma_half<2, 64>(aH + 2 * H1C + wid * 64, wfP, acc);
            #pragma unroll
            for (int mt = 0; mt < 2; ++mt)
                #pragma unroll
                for (int n = 0; n < 4; ++n) {
                    int rr = mt * 16 + (lane >> 2);
                    float* p = pt + wid * 1056 + rr * 33 + n * 8 + tig * 2;
                    p[0]          = acc[mt][n][0];
                    p[1]          = acc[mt][n][1];
                    p[8 * 33]     = acc[mt][n][2];
                    p[8 * 33 + 1] = acc[mt][n][3];
                }
        }
        __syncthreads();

        // ---- reduce partials + bias; rank writes its half of rows to gmem; feed back x ----
        for (int o = tid; o < ROWS * DIM; o += NT) {
            int r = o / DIM, d = o - r * DIM;
            float y = __ldg(b_proj + d);
            #pragma unroll
            for (int w8 = 0; w8 < 8; ++w8) y += pt[w8 * 1056 + r * 33 + d];
            if ((uint32_t)(r >> 4) == cr)
                out[(size_t)(r0 + r) * (TST * DIM) + (size_t)t * DIM + d] = y;
            Ah[r * AS + d] = f16u(y);
        }
        __syncthreads();
    }
}

extern "C" void kernel_launch(void* const* d_in, const int* in_sizes, int n_in,
                              void* d_out, int out_size) {
    const int wbase = (n_in >= 17) ? 3 : 2;

    const float* z      = (const float*)d_in[0];
    const float* w_lh   = (const float*)d_in[wbase + 0];
    const float* b_lh   = (const float*)d_in[wbase + 1];
    const float* w_lc   = (const float*)d_in[wbase + 2];
    const float* b_lc   = (const float*)d_in[wbase + 3];
    const float* w_ih0  = (const float*)d_in[wbase + 4];
    const float* w_hh0  = (const float*)d_in[wbase + 5];
    const float* b_ih0  = (const float*)d_in[wbase + 6];
    const float* b_hh0  = (const float*)d_in[wbase + 7];
    const float* w_ih1  = (const float*)d_in[wbase + 8];
    const float* w_hh1  = (const float*)d_in[wbase + 9];
    const float* b_ih1  = (const float*)d_in[wbase + 10];
    const float* b_hh1  = (const float*)d_in[wbase + 11];
    const float* w_proj = (const float*)d_in[wbase + 12];
    const float* b_proj = (const float*)d_in[wbase + 13];

    static bool attr_set = false;
    if (!attr_set) {
        cudaFuncSetAttribute(decoder_kernel,
                             cudaFuncAttributeMaxDynamicSharedMemorySize, SMEM_BYTES);
        attr_set = true;
    }

    repack_kernel<<<512, 256>>>(w_ih0, w_hh0, b_ih0, b_hh0,
                                w_ih1, w_hh1, b_ih1, b_hh1, w_proj);
    decoder_kernel<<<NCTA, NT, SMEM_BYTES>>>(z, w_lh, b_lh, w_lc, b_lc,
                                             b_proj, (float*)d_out);
}

// round 14
// speedup vs baseline: 1.6601x; 1.2676x over previous
#include <cuda_runtime.h>
#include <cuda_fp16.h>
#include <cstdint>

#define BATCH   2048
#define LATD    32
#define HID     256
#define DIM     20
#define TST     512

#define ROWS    32                 // batch rows per CLUSTER
#define CLUSTER 2
#define NCTA    ((BATCH / ROWS) * CLUSTER)   // 128
#define NT      512                // 16 warps per CTA, each owns 32 gate columns
#define NSLOT   32                 // global column-owner slots (2 CTAs x 16)

#define KS0     18                 // layer0: cols 0..287  (x|1|0|h0)
#define KS1     33                 // layer1: cols 16..543 (..|1|..|h0|h1)
#define AS      552                // u16 elements per activation row
#define ROWB    (AS * 2)           // bytes per row
#define MTOFF   (16 * ROWB)        // m-tile 1 byte offset
#define H0C     32
#define H1C     288

#define SMEM_BYTES (32*AS*2 + 8*32*33*4 + ROWS*LATD*4)   // 73216

// ---------------- fragment-major packed fp16 weights (repacked each launch) ----------------
// gates layout: [slot][ks][pp(2)][lane]  (uint4 = 2 n-tiles x {b0,b1})
__device__ uint4 g_W0[NSLOT * KS0 * 2 * 32];
__device__ uint4 g_W1[NSLOT * KS1 * 2 * 32];
__device__ uint4 g_PJ[8 * 2 * 2 * 32];      // [pk][ks][pp][lane]

// ---------------- helpers ----------------
__device__ __forceinline__ float tanh_fast(float x) {   // HW tanh (sigmoid path only)
    float r; asm("tanh.approx.f32 %0, %1;" : "=f"(r) : "f"(x)); return r;
}
__device__ __forceinline__ float sigm(float x) {
    return fmaf(0.5f, tanh_fast(0.5f * x), 0.5f);
}
__device__ __forceinline__ float tanh_(float x) {       // accurate (small-value sensitive)
    float e = __expf(2.f * x);
    return 1.f - __fdividef(2.f, e + 1.f);
}
__device__ __forceinline__ unsigned short f16u(float x) {
    return __half_as_ushort(__float2half_rn(x));
}
__device__ __forceinline__ uint32_t f16x2(float a, float b) {
    return (uint32_t)f16u(a) | ((uint32_t)f16u(b) << 16);
}
__device__ __forceinline__ uint32_t smem_u32(const void* p) {
    uint32_t a;
    asm("{ .reg .u64 t; cvta.to.shared.u64 t, %1; cvt.u32.u64 %0, t; }" : "=r"(a) : "l"(p));
    return a;
}
__device__ __forceinline__ uint32_t mapa_sh(uint32_t addr, uint32_t rank) {
    uint32_t r;
    asm("mapa.shared::cluster.u32 %0, %1, %2;" : "=r"(r) : "r"(addr), "r"(rank));
    return r;
}
__device__ __forceinline__ void st_remote_u32(uint32_t addr, uint32_t v) {
    asm volatile("st.shared::cluster.u32 [%0], %1;" :: "r"(addr), "r"(v) : "memory");
}
__device__ __forceinline__ void cluster_sync_() {
    asm volatile("barrier.cluster.arrive.aligned;" ::: "memory");
    asm volatile("barrier.cluster.wait.aligned;" ::: "memory");
}
__device__ __forceinline__ void ldsm4(uint32_t& r0, uint32_t& r1, uint32_t& r2, uint32_t& r3,
                                      uint32_t a) {
    asm volatile("ldmatrix.sync.aligned.m8n8.x4.shared.b16 {%0,%1,%2,%3}, [%4];"
                 : "=r"(r0), "=r"(r1), "=r"(r2), "=r"(r3) : "r"(a));
}
__device__ __forceinline__ void mma16816(float* c, uint32_t a0, uint32_t a1, uint32_t a2,
                                         uint32_t a3, uint32_t b0, uint32_t b1) {
    asm volatile(
        "mma.sync.aligned.m16n8k16.row.col.f32.f16.f16.f32 "
        "{%0,%1,%2,%3}, {%4,%5,%6,%7}, {%8,%9}, {%0,%1,%2,%3};"
        : "+f"(c[0]), "+f"(c[1]), "+f"(c[2]), "+f"(c[3])
        : "r"(a0), "r"(a1), "r"(a2), "r"(a3), "r"(b0), "r"(b1));
}

// ---------------- repack: weight element accessors (kc = activation column) ----------------
__device__ __forceinline__ float W0val(int kc, int n,
                                       const float* w_ih0, const float* w_hh0,
                                       const float* b_ih0, const float* b_hh0) {
    int u = n >> 2, g = n & 3, row = g * HID + u;
    if (kc < DIM)  return w_ih0[row * DIM + kc];
    if (kc == 20)  return b_ih0[row] + b_hh0[row];
    if (kc < 32)   return 0.f;
    return w_hh0[row * HID + (kc - 32)];
}
__device__ __forceinline__ float W1val(int kc, int n,
                                       const float* w_ih1, const float* w_hh1,
                                       const float* b_ih1, const float* b_hh1) {
    int u = n >> 2, g = n & 3, row = g * HID + u;
    if (kc == 20)  return b_ih1[row] + b_hh1[row];
    if (kc >= 288) return w_hh1[row * HID + (kc - 288)];
    if (kc >= 32)  return w_ih1[row * HID + (kc - 32)];
    return 0.f;
}

__global__ void repack_kernel(const float* __restrict__ w_ih0, const float* __restrict__ w_hh0,
                              const float* __restrict__ b_ih0, const float* __restrict__ b_hh0,
                              const float* __restrict__ w_ih1, const float* __restrict__ w_hh1,
                              const float* __restrict__ b_ih1, const float* __restrict__ b_hh1,
                              const float* __restrict__ w_proj) {
    const int stride = gridDim.x * blockDim.x;
    const int base   = blockIdx.x * blockDim.x + threadIdx.x;

    const int N0 = NSLOT * KS0 * 2 * 32;
    for (int idx = base; idx < N0; idx += stride) {
        int lane = idx & 31, t = idx >> 5;
        int pp = t & 1; t >>= 1;
        int ks = t % KS0, s = t / KS0;
        int na = s * 32 + pp * 16 + (lane >> 2);
        int nb = na + 8;
        int kc = ks * 16 + (lane & 3) * 2;
        uint4 v;
        v.x = f16x2(W0val(kc,     na, w_ih0, w_hh0, b_ih0, b_hh0),
                    W0val(kc + 1, na, w_ih0, w_hh0, b_ih0, b_hh0));
        v.y = f16x2(W0val(kc + 8, na, w_ih0, w_hh0, b_ih0, b_hh0),
                    W0val(kc + 9, na, w_ih0, w_hh0, b_ih0, b_hh0));
        v.z = f16x2(W0val(kc,     nb, w_ih0, w_hh0, b_ih0, b_hh0),
                    W0val(kc + 1, nb, w_ih0, w_hh0, b_ih0, b_hh0));
        v.w = f16x2(W0val(kc + 8, nb, w_ih0, w_hh0, b_ih0, b_hh0),
                    W0val(kc + 9, nb, w_ih0, w_hh0, b_ih0, b_hh0));
        g_W0[idx] = v;
    }
    const int N1 = NSLOT * KS1 * 2 * 32;
    for (int idx = base; idx < N1; idx += stride) {
        int lane = idx & 31, t = idx >> 5;
        int pp = t & 1; t >>= 1;
        int ks = t % KS1, s = t / KS1;
        int na = s * 32 + pp * 16 + (lane >> 2);
        int nb = na + 8;
        int kc = 16 + ks * 16 + (lane & 3) * 2;
        uint4 v;
        v.x = f16x2(W1val(kc,     na, w_ih1, w_hh1, b_ih1, b_hh1),
                    W1val(kc + 1, na, w_ih1, w_hh1, b_ih1, b_hh1));
        v.y = f16x2(W1val(kc + 8, na, w_ih1, w_hh1, b_ih1, b_hh1),
                    W1val(kc + 9, na, w_ih1, w_hh1, b_ih1, b_hh1));
        v.z = f16x2(W1val(kc,     nb, w_ih1, w_hh1, b_ih1, b_hh1),
                    W1val(kc + 1, nb, w_ih1, w_hh1, b_ih1, b_hh1));
        v.w = f16x2(W1val(kc + 8, nb, w_ih1, w_hh1, b_ih1, b_hh1),
                    W1val(kc + 9, nb, w_ih1, w_hh1, b_ih1, b_hh1));
        g_W1[idx] = v;
    }
    const int NP = 8 * 2 * 2 * 32;
    for (int idx = base; idx < NP; idx += stride) {
        int lane = idx & 31, t = idx >> 5;
        int pp = t & 1; t >>= 1;
        int ks = t & 1; t >>= 1;
        int w  = t;                                   // 0..7 (proj K-slice)
        int na = pp * 16 + (lane >> 2);
        int nb = na + 8;
        int kc = w * 32 + ks * 16 + (lane & 3) * 2;
        auto PV = [&](int n, int k) -> float {
            return (n < DIM) ? w_proj[n * HID + k] : 0.f;
        };
        uint4 v;
        v.x = f16x2(PV(na, kc),     PV(na, kc + 1));
        v.y = f16x2(PV(na, kc + 8), PV(na, kc + 9));
        v.z = f16x2(PV(nb, kc),     PV(nb, kc + 1));
        v.w = f16x2(PV(nb, kc + 8), PV(nb, kc + 9));
        g_PJ[idx] = v;
    }
}

// ---------------- single-pass fp16 MMA: 4 n-tiles x 2 m-tiles, B prefetch ----------------
template <int KSTEPS>
__device__ __forceinline__ void mma_gates(uint32_t aHi,
                                          const uint4* __restrict__ wf,
                                          float (&acc)[2][4][4]) {
    #pragma unroll
    for (int mt = 0; mt < 2; ++mt)
        #pragma unroll
        for (int n = 0; n < 4; ++n)
            #pragma unroll
            for (int i = 0; i < 4; ++i) acc[mt][n][i] = 0.f;

    uint4 B0 = __ldg(wf), B1 = __ldg(wf + 32);

    #pragma unroll 2
    for (int ks = 0; ks < KSTEPS; ++ks) {
        uint4 B0n, B1n;
        if (ks + 1 < KSTEPS) {
            B0n = __ldg(wf + (size_t)(ks + 1) * 64);
            B1n = __ldg(wf + (size_t)(ks + 1) * 64 + 32);
        }
        uint32_t h0, h1, h2, h3, h4, h5, h6, h7;
        ldsm4(h0, h1, h2, h3, aHi + ks * 32);
        ldsm4(h4, h5, h6, h7, aHi + MTOFF + ks * 32);
        mma16816(acc[0][0], h0, h1, h2, h3, B0.x, B0.y);
        mma16816(acc[1][0], h4, h5, h6, h7, B0.x, B0.y);
        mma16816(acc[0][1], h0, h1, h2, h3, B0.z, B0.w);
        mma16816(acc[1][1], h4, h5, h6, h7, B0.z, B0.w);
        mma16816(acc[0][2], h0, h1, h2, h3, B1.x, B1.y);
        mma16816(acc[1][2], h4, h5, h6, h7, B1.x, B1.y);
        mma16816(acc[0][3], h0, h1, h2, h3, B1.z, B1.w);
        mma16816(acc[1][3], h4, h5, h6, h7, B1.z, B1.w);
        B0 = B0n;  B1 = B1n;
    }
}

// ---------------- projection MMA: single m-tile, 4 n-tiles, K=32 (2 ks) ----------------
__device__ __forceinline__ void mma_proj(uint32_t aHi,
                                         const uint4* __restrict__ wf,
                                         float (&acc)[4][4]) {
    #pragma unroll
    for (int n = 0; n < 4; ++n)
        #pragma unroll
        for (int i = 0; i < 4; ++i) acc[n][i] = 0.f;
    #pragma unroll
    for (int ks = 0; ks < 2; ++ks) {
        uint4 B0 = __ldg(wf + (size_t)ks * 64);
        uint4 B1 = __ldg(wf + (size_t)ks * 64 + 32);
        uint32_t h0, h1, h2, h3;
        ldsm4(h0, h1, h2, h3, aHi + ks * 32);
        mma16816(acc[0], h0, h1, h2, h3, B0.x, B0.y);
        mma16816(acc[1], h0, h1, h2, h3, B0.z, B0.w);
        mma16816(acc[2], h0, h1, h2, h3, B1.x, B1.y);
        mma16816(acc[3], h0, h1, h2, h3, B1.z, B1.w);
    }
}

// ---------------- LSTM epilogue: gate regroup via lane-pair shuffle ----------------
__device__ __forceinline__ void lstm_epi(float (&acc)[2][4][4], int odd,
                                         float (&cs)[2][4], uint32_t (&hp)[2][4]) {
    #pragma unroll
    for (int mt = 0; mt < 2; ++mt) {
        #pragma unroll
        for (int n = 0; n < 4; ++n) {
            float a0 = acc[mt][n][0], a1 = acc[mt][n][1];
            float a2 = acc[mt][n][2], a3 = acc[mt][n][3];
            float t0 = __shfl_xor_sync(0xffffffffu, a0, 1);
            float t1 = __shfl_xor_sync(0xffffffffu, a1, 1);
            float t2 = __shfl_xor_sync(0xffffffffu, a2, 1);
            float t3 = __shfl_xor_sync(0xffffffffu, a3, 1);
            float gi = odd ? t2 : a0;
            float gf = odd ? t3 : a1;
            float gg = odd ? a2 : t0;
            float go = odd ? a3 : t1;
            float c = sigm(gf) * cs[mt][n] + sigm(gi) * tanh_(gg);
            cs[mt][n] = c;
            float h = sigm(go) * tanh_(c);
            hp[mt][n] = (uint32_t)f16u(h);
        }
    }
}

// ---------------- main persistent clustered kernel ----------------
__global__ void __launch_bounds__(NT, 1) __cluster_dims__(CLUSTER, 1, 1)
decoder_kernel(const float* __restrict__ z,
               const float* __restrict__ w_lh, const float* __restrict__ b_lh,
               const float* __restrict__ w_lc, const float* __restrict__ b_lc,
               const float* __restrict__ b_proj,
               float* __restrict__ out) {
    extern __shared__ __align__(16) char smem[];
    uint16_t* Ah  = (uint16_t*)smem;                 // [32][AS] fp16 activations
    float*    pt  = (float*)(Ah + 32 * AS);          // [8][32][33] proj partials
    float*    z_s = pt + 8 * 32 * 33;                // [32][32]

    const int tid  = threadIdx.x;
    const int wid  = tid >> 5;
    const int lane = tid & 31;
    const int tig  = lane & 3;
    const int odd  = lane & 1;
    uint32_t cr;
    asm("mov.u32 %0, %%cluster_ctarank;" : "=r"(cr));
    const int slot = (int)cr * 16 + wid;             // 0..31 column-owner slot
    const int r0   = (blockIdx.x / CLUSTER) * ROWS;
    const int ubase  = slot * 8 + (tig >> 1);
    const int rbaseA = (lane >> 2) + (odd ? 8 : 0);
    const int myrow[2] = { rbaseA, 16 + rbaseA };
    const bool packlead = (lane & 2) == 0;           // pairs lanes via xor 2

    // ---- stage z; init x-pad cols 0..31 (col 20 = fp16 1.0 bias column) ----
    for (int i = tid; i < ROWS * LATD; i += NT) z_s[i] = z[(size_t)r0 * LATD + i];
    for (int i = tid; i < 32 * 32; i += NT) {
        int r = i >> 5, c = i & 31;
        Ah[r * AS + c] = (c == 20) ? (uint16_t)0x3C00 : (uint16_t)0;
    }
    __syncthreads();

    // ---- c-state init in C-fragment layout (own units, both m-tiles) ----
    float c0st[2][4], c1st[2][4];
    #pragma unroll
    for (int mt = 0; mt < 2; ++mt)
        #pragma unroll
        for (int nt = 0; nt < 4; ++nt) {
            int u = ubase + nt * 2;
            float s0 = b_lc[u], s1 = b_lc[HID + u];
            for (int k = 0; k < LATD; ++k) {
                float wa = __ldg(w_lc + (size_t)u * LATD + k);
                float wb = __ldg(w_lc + (size_t)(HID + u) * LATD + k);
                float zv = z_s[myrow[mt] * LATD + k];
                s0 = fmaf(zv, wa, s0);  s1 = fmaf(zv, wb, s1);
            }
            c0st[mt][nt] = s0;  c1st[mt][nt] = s1;
        }

    // ---- h-state init into Ah: each CTA fills the FULL A (redundant, init-only) ----
    {
        int u2 = tid & 255, rb = (tid >> 8) * 16;
        float h0v[16], h1v[16];
        #pragma unroll
        for (int r = 0; r < 16; ++r) { h0v[r] = b_lh[u2]; h1v[r] = b_lh[HID + u2]; }
        for (int k = 0; k < LATD; ++k) {
            float wa = __ldg(w_lh + (size_t)u2 * LATD + k);
            float wb = __ldg(w_lh + (size_t)(HID + u2) * LATD + k);
            #pragma unroll
            for (int r = 0; r < 16; ++r) {
                float zv = z_s[(rb + r) * LATD + k];
                h0v[r] = fmaf(zv, wa, h0v[r]);
                h1v[r] = fmaf(zv, wb, h1v[r]);
            }
        }
        #pragma unroll
        for (int r = 0; r < 16; ++r) {
            Ah[(rb + r) * AS + H0C + u2] = f16u(h0v[r]);
            Ah[(rb + r) * AS + H1C + u2] = f16u(h1v[r]);
        }
    }

    // ---- projection-reduce assignments (fixed across t) ----
    int pr_[2], pd_[2];
    float pb_[2];
    int pn = 0;
    for (int o = tid; o < ROWS * DIM; o += NT) {
        pr_[pn] = o / DIM;
        pd_[pn] = o - pr_[pn] * DIM;
        pb_[pn] = b_proj[pd_[pn]];
        ++pn;
    }
    __syncthreads();

    const uint32_t AhB = smem_u32(Ah);
    const uint32_t pAh = mapa_sh(AhB, cr ^ 1u);
    const uint32_t aH = AhB + (lane & 15) * ROWB + (lane >> 4) * 16;
    const uint4* wf0 = g_W0 + (size_t)slot * KS0 * 64 + lane;
    const uint4* wf1 = g_W1 + (size_t)slot * KS1 * 64 + lane;
    const int pk = wid >> 1;                         // proj K-slice 0..7
    const int pm = wid & 1;                          // proj m-tile
    const uint4* wfP = g_PJ + (size_t)pk * 128 + lane;
    const uint32_t aPH = aH + pm * MTOFF + 2 * H1C + pk * 64;

    cluster_sync_();

    // =============================== time loop ===============================
    for (int t = 0; t < TST; ++t) {
        uint32_t hp[2][4];
        float acc[2][4][4];

        // ---- layer 0 : reads cols 0..287 ----
        mma_gates<KS0>(aH, wf0, acc);
        lstm_epi(acc, odd, c0st, hp);
        cluster_sync_();                              // both CTAs done reading h0_old
        #pragma unroll
        for (int mt = 0; mt < 2; ++mt)
            #pragma unroll
            for (int nt = 0; nt < 4; ++nt) {
                uint32_t oth = __shfl_xor_sync(0xffffffffu, hp[mt][nt], 2);
                if (packlead) {
                    uint32_t v = (hp[mt][nt] & 0xffffu) | (oth << 16);
                    int row = myrow[mt], u = slot * 8 + nt * 2;       // u even
                    uint32_t off = (uint32_t)(row * AS + H0C + u) * 2;
                    *reinterpret_cast<uint32_t*>(&Ah[row * AS + H0C + u]) = v;
                    st_remote_u32(pAh + off, v);
                }
            }
        cluster_sync_();                              // new h0 visible cluster-wide

        // ---- layer 1 : reads cols 16..543 ----
        mma_gates<KS1>(aH + 32, wf1, acc);
        lstm_epi(acc, odd, c1st, hp);
        cluster_sync_();                              // both CTAs done reading h1_old
        #pragma unroll
        for (int mt = 0; mt < 2; ++mt)
            #pragma unroll
            for (int nt = 0; nt < 4; ++nt) {
                uint32_t oth = __shfl_xor_sync(0xffffffffu, hp[mt][nt], 2);
                if (packlead) {
                    uint32_t v = (hp[mt][nt] & 0xffffu) | (oth << 16);
                    int row = myrow[mt], u = slot * 8 + nt * 2;
                    uint32_t off = (uint32_t)(row * AS + H1C + u) * 2;
                    *reinterpret_cast<uint32_t*>(&Ah[row * AS + H1C + u]) = v;
                    st_remote_u32(pAh + off, v);
                }
            }
        cluster_sync_();                              // new h1 visible cluster-wide

        // ---- projection MMA: 8 K-slices x 2 m-tiles across 16 warps ----
        {
            float pac[4][4];
            mma_proj(aPH, wfP, pac);
            #pragma unroll
            for (int n = 0; n < 4; ++n) {
                int rr = pm * 16 + (lane >> 2);
                float* p = pt + pk * 1056 + rr * 33 + n * 8 + tig * 2;
                p[0]          = pac[n][0];
                p[1]          = pac[n][1];
                p[8 * 33]     = pac[n][2];
                p[8 * 33 + 1] = pac[n][3];
            }
        }
        __syncthreads();

        // ---- reduce partials + bias; rank writes its half of rows to gmem; feed back x ----
        for (int i2 = 0; i2 < pn; ++i2) {
            int r = pr_[i2], d = pd_[i2];
            float y = pb_[i2];
            #pragma unroll
            for (int w8 = 0; w8 < 8; ++w8) y += pt[w8 * 1056 + r * 33 + d];
            if ((uint32_t)(r >> 4) == cr)
                out[(size_t)(r0 + r) * (TST * DIM) + (size_t)t * DIM + d] = y;
            Ah[r * AS + d] = f16u(y);
        }
        __syncthreads();
    }
}

extern "C" void kernel_launch(void* const* d_in, const int* in_sizes, int n_in,
                              void* d_out, int out_size) {
    const int wbase = (n_in >= 17) ? 3 : 2;

    const float* z      = (const float*)d_in[0];
    const float* w_lh   = (const float*)d_in[wbase + 0];
    const float* b_lh   = (const float*)d_in[wbase + 1];
    const float* w_lc   = (const float*)d_in[wbase + 2];
    const float* b_lc   = (const float*)d_in[wbase + 3];
    const float* w_ih0  = (const float*)d_in[wbase + 4];
    const float* w_hh0  = (const float*)d_in[wbase + 5];
    const float* b_ih0  = (const float*)d_in[wbase + 6];
    const float* b_hh0  = (const float*)d_in[wbase + 7];
    const float* w_ih1  = (const float*)d_in[wbase + 8];
    const float* w_hh1  = (const float*)d_in[wbase + 9];
    const float* b_ih1  = (const float*)d_in[wbase + 10];
    const float* b_hh1  = (const float*)d_in[wbase + 11];
    const float* w_proj = (const float*)d_in[wbase + 12];
    const float* b_proj = (const float*)d_in[wbase + 13];

    static bool attr_set = false;
    if (!attr_set) {
        cudaFuncSetAttribute(decoder_kernel,
                             cudaFuncAttributeMaxDynamicSharedMemorySize, SMEM_BYTES);
        attr_set = true;
    }

    repack_kernel<<<512, 256>>>(w_ih0, w_hh0, b_ih0, b_hh0,
                                w_ih1, w_hh1, b_ih1, b_hh1, w_proj);
    decoder_kernel<<<NCTA, NT, SMEM_BYTES>>>(z, w_lh, b_lh, w_lc, b_lc,
                                             b_proj, (float*)d_out);
}

// round 15
// speedup vs baseline: 1.8269x; 1.1005x over previous
#include <cuda_runtime.h>
#include <cuda_fp16.h>
#include <cstdint>

#define BATCH   2048
#define LATD    32
#define HID     256
#define DIM     20
#define TST     512

#define ROWS    32                 // batch rows per CLUSTER
#define CLUSTER 2
#define NCTA    ((BATCH / ROWS) * CLUSTER)   // 128
#define NT      512                // 16 warps per CTA, each owns 32 gate columns
#define NSLOT   32                 // global column-owner slots (2 CTAs x 16)

#define KS0     18                 // layer0: x-pad (2 ks) + h0 (16 ks)
#define KS1     32                 // layer1: h0_new (16 ks) + h1_old (16 ks)
#define AS      1064               // u16 elements per activation row (ping-pong buffers)
#define ROWB    (AS * 2)           // 2128 bytes per row (532 words; %32 == 20, same as R14)
#define MTOFF   (16 * ROWB)

// activation column bases (u16 units): x 0..31 (bias col 20), h0[p] 32+p*256, h1[p] 544+p*256
#define SMEM_BYTES (32*AS*2 + 8*32*33*4 + ROWS*LATD*4)   // 105984

// ---------------- fragment-major packed fp16 weights (repacked each launch) ----------------
// gates layout: [slot][ks][pp(2)][lane]  (uint4 = 2 n-tiles x {b0,b1})
__device__ uint4 g_W0[NSLOT * KS0 * 2 * 32];
__device__ uint4 g_W1[NSLOT * KS1 * 2 * 32];   // ks 0..15 = h0 cols, ks 16..31 = h1 cols
__device__ uint4 g_PJ[8 * 2 * 2 * 32];         // [pk][ks][pp][lane]

// ---------------- helpers ----------------
__device__ __forceinline__ float tanh_fast(float x) {
    float r; asm("tanh.approx.f32 %0, %1;" : "=f"(r) : "f"(x)); return r;
}
__device__ __forceinline__ float sigm(float x) {
    return fmaf(0.5f, tanh_fast(0.5f * x), 0.5f);
}
__device__ __forceinline__ float tanh_(float x) {
    float e = __expf(2.f * x);
    return 1.f - __fdividef(2.f, e + 1.f);
}
__device__ __forceinline__ unsigned short f16u(float x) {
    return __half_as_ushort(__float2half_rn(x));
}
__device__ __forceinline__ uint32_t f16x2(float a, float b) {
    return (uint32_t)f16u(a) | ((uint32_t)f16u(b) << 16);
}
__device__ __forceinline__ uint32_t smem_u32(const void* p) {
    uint32_t a;
    asm("{ .reg .u64 t; cvta.to.shared.u64 t, %1; cvt.u32.u64 %0, t; }" : "=r"(a) : "l"(p));
    return a;
}
__device__ __forceinline__ uint32_t mapa_sh(uint32_t addr, uint32_t rank) {
    uint32_t r;
    asm("mapa.shared::cluster.u32 %0, %1, %2;" : "=r"(r) : "r"(addr), "r"(rank));
    return r;
}
__device__ __forceinline__ void st_remote_u32(uint32_t addr, uint32_t v) {
    asm volatile("st.shared::cluster.u32 [%0], %1;" :: "r"(addr), "r"(v) : "memory");
}
__device__ __forceinline__ void cluster_sync_() {
    asm volatile("barrier.cluster.arrive.aligned;" ::: "memory");
    asm volatile("barrier.cluster.wait.aligned;" ::: "memory");
}
__device__ __forceinline__ void cluster_arrive_() {
    asm volatile("barrier.cluster.arrive.aligned;" ::: "memory");
}
__device__ __forceinline__ void cluster_wait_() {
    asm volatile("barrier.cluster.wait.aligned;" ::: "memory");
}
__device__ __forceinline__ void prefetchL1(const void* p) {
    asm volatile("prefetch.global.L1 [%0];" :: "l"(p));
}
__device__ __forceinline__ void ldsm4(uint32_t& r0, uint32_t& r1, uint32_t& r2, uint32_t& r3,
                                      uint32_t a) {
    asm volatile("ldmatrix.sync.aligned.m8n8.x4.shared.b16 {%0,%1,%2,%3}, [%4];"
                 : "=r"(r0), "=r"(r1), "=r"(r2), "=r"(r3) : "r"(a));
}
__device__ __forceinline__ void mma16816(float* c, uint32_t a0, uint32_t a1, uint32_t a2,
                                         uint32_t a3, uint32_t b0, uint32_t b1) {
    asm volatile(
        "mma.sync.aligned.m16n8k16.row.col.f32.f16.f16.f32 "
        "{%0,%1,%2,%3}, {%4,%5,%6,%7}, {%8,%9}, {%0,%1,%2,%3};"
        : "+f"(c[0]), "+f"(c[1]), "+f"(c[2]), "+f"(c[3])
        : "r"(a0), "r"(a1), "r"(a2), "r"(a3), "r"(b0), "r"(b1));
}

// ---------------- repack: weight element accessors ----------------
__device__ __forceinline__ float W0val(int kc, int n,
                                       const float* w_ih0, const float* w_hh0,
                                       const float* b_ih0, const float* b_hh0) {
    int u = n >> 2, g = n & 3, row = g * HID + u;
    if (kc < DIM)  return w_ih0[row * DIM + kc];
    if (kc == 20)  return b_ih0[row] + b_hh0[row];
    if (kc < 32)   return 0.f;
    return w_hh0[row * HID + (kc - 32)];
}
// layer1: kc in [32..543]: 32..287 -> w_ih1 (h0), 288..543 -> w_hh1 (h1). No bias column.
__device__ __forceinline__ float W1val(int kc, int n,
                                       const float* w_ih1, const float* w_hh1) {
    int u = n >> 2, g = n & 3, row = g * HID + u;
    if (kc >= 288) return w_hh1[row * HID + (kc - 288)];
    return w_ih1[row * HID + (kc - 32)];
}

__global__ void repack_kernel(const float* __restrict__ w_ih0, const float* __restrict__ w_hh0,
                              const float* __restrict__ b_ih0, const float* __restrict__ b_hh0,
                              const float* __restrict__ w_ih1, const float* __restrict__ w_hh1,
                              const float* __restrict__ w_proj) {
    const int stride = gridDim.x * blockDim.x;
    const int base   = blockIdx.x * blockDim.x + threadIdx.x;

    const int N0 = NSLOT * KS0 * 2 * 32;
    for (int idx = base; idx < N0; idx += stride) {
        int lane = idx & 31, t = idx >> 5;
        int pp = t & 1; t >>= 1;
        int ks = t % KS0, s = t / KS0;
        int na = s * 32 + pp * 16 + (lane >> 2);
        int nb = na + 8;
        int kc = ks * 16 + (lane & 3) * 2;
        uint4 v;
        v.x = f16x2(W0val(kc,     na, w_ih0, w_hh0, b_ih0, b_hh0),
                    W0val(kc + 1, na, w_ih0, w_hh0, b_ih0, b_hh0));
        v.y = f16x2(W0val(kc + 8, na, w_ih0, w_hh0, b_ih0, b_hh0),
                    W0val(kc + 9, na, w_ih0, w_hh0, b_ih0, b_hh0));
        v.z = f16x2(W0val(kc,     nb, w_ih0, w_hh0, b_ih0, b_hh0),
                    W0val(kc + 1, nb, w_ih0, w_hh0, b_ih0, b_hh0));
        v.w = f16x2(W0val(kc + 8, nb, w_ih0, w_hh0, b_ih0, b_hh0),
                    W0val(kc + 9, nb, w_ih0, w_hh0, b_ih0, b_hh0));
        g_W0[idx] = v;
    }
    const int N1 = NSLOT * KS1 * 2 * 32;
    for (int idx = base; idx < N1; idx += stride) {
        int lane = idx & 31, t = idx >> 5;
        int pp = t & 1; t >>= 1;
        int ks = t % KS1, s = t / KS1;
        int na = s * 32 + pp * 16 + (lane >> 2);
        int nb = na + 8;
        int kc = 32 + ks * 16 + (lane & 3) * 2;
        uint4 v;
        v.x = f16x2(W1val(kc,     na, w_ih1, w_hh1), W1val(kc + 1, na, w_ih1, w_hh1));
        v.y = f16x2(W1val(kc + 8, na, w_ih1, w_hh1), W1val(kc + 9, na, w_ih1, w_hh1));
        v.z = f16x2(W1val(kc,     nb, w_ih1, w_hh1), W1val(kc + 1, nb, w_ih1, w_hh1));
        v.w = f16x2(W1val(kc + 8, nb, w_ih1, w_hh1), W1val(kc + 9, nb, w_ih1, w_hh1));
        g_W1[idx] = v;
    }
    const int NP = 8 * 2 * 2 * 32;
    for (int idx = base; idx < NP; idx += stride) {
        int lane = idx & 31, t = idx >> 5;
        int pp = t & 1; t >>= 1;
        int ks = t & 1; t >>= 1;
        int w  = t;                                   // 0..7 (proj K-slice)
        int na = pp * 16 + (lane >> 2);
        int nb = na + 8;
        int kc = w * 32 + ks * 16 + (lane & 3) * 2;
        auto PV = [&](int n, int k) -> float {
            return (n < DIM) ? w_proj[n * HID + k] : 0.f;
        };
        uint4 v;
        v.x = f16x2(PV(na, kc),     PV(na, kc + 1));
        v.y = f16x2(PV(na, kc + 8), PV(na, kc + 9));
        v.z = f16x2(PV(nb, kc),     PV(nb, kc + 1));
        v.w = f16x2(PV(nb, kc + 8), PV(nb, kc + 9));
        g_PJ[idx] = v;
    }
}

// ---------------- gate MMA segment: 4 n-tiles x 2 m-tiles, accumulating ----------------
template <int KSTEPS>
__device__ __forceinline__ void mma_seg(uint32_t aHi,
                                        const uint4* __restrict__ wf,
                                        float (&acc)[2][4][4]) {
    uint4 B0 = __ldg(wf), B1 = __ldg(wf + 32);
    #pragma unroll 2
    for (int ks = 0; ks < KSTEPS; ++ks) {
        if (ks + 2 < KSTEPS) {
            prefetchL1(wf + (size_t)(ks + 2) * 64);
            prefetchL1(wf + (size_t)(ks + 2) * 64 + 32);
        }
        uint4 B0n, B1n;
        if (ks + 1 < KSTEPS) {
            B0n = __ldg(wf + (size_t)(ks + 1) * 64);
            B1n = __ldg(wf + (size_t)(ks + 1) * 64 + 32);
        }
        uint32_t h0, h1, h2, h3, h4, h5, h6, h7;
        ldsm4(h0, h1, h2, h3, aHi + ks * 32);
        ldsm4(h4, h5, h6, h7, aHi + MTOFF + ks * 32);
        mma16816(acc[0][0], h0, h1, h2, h3, B0.x, B0.y);
        mma16816(acc[1][0], h4, h5, h6, h7, B0.x, B0.y);
        mma16816(acc[0][1], h0, h1, h2, h3, B0.z, B0.w);
        mma16816(acc[1][1], h4, h5, h6, h7, B0.z, B0.w);
        mma16816(acc[0][2], h0, h1, h2, h3, B1.x, B1.y);
        mma16816(acc[1][2], h4, h5, h6, h7, B1.x, B1.y);
        mma16816(acc[0][3], h0, h1, h2, h3, B1.z, B1.w);
        mma16816(acc[1][3], h4, h5, h6, h7, B1.z, B1.w);
        B0 = B0n;  B1 = B1n;
    }
}

// ---------------- projection MMA: single m-tile, 4 n-tiles, K=32 (2 ks) ----------------
__device__ __forceinline__ void mma_proj(uint32_t aHi,
                                         const uint4* __restrict__ wf,
                                         float (&acc)[4][4]) {
    #pragma unroll
    for (int n = 0; n < 4; ++n)
        #pragma unroll
        for (int i = 0; i < 4; ++i) acc[n][i] = 0.f;
    #pragma unroll
    for (int ks = 0; ks < 2; ++ks) {
        uint4 B0 = __ldg(wf + (size_t)ks * 64);
        uint4 B1 = __ldg(wf + (size_t)ks * 64 + 32);
        uint32_t h0, h1, h2, h3;
        ldsm4(h0, h1, h2, h3, aHi + ks * 32);
        mma16816(acc[0], h0, h1, h2, h3, B0.x, B0.y);
        mma16816(acc[1], h0, h1, h2, h3, B0.z, B0.w);
        mma16816(acc[2], h0, h1, h2, h3, B1.x, B1.y);
        mma16816(acc[3], h0, h1, h2, h3, B1.z, B1.w);
    }
}

// ---------------- LSTM epilogue: gate regroup via lane-pair shuffle ----------------
__device__ __forceinline__ void lstm_epi(float (&acc)[2][4][4], int odd,
                                         float (&cs)[2][4], uint32_t (&hp)[2][4]) {
    #pragma unroll
    for (int mt = 0; mt < 2; ++mt) {
        #pragma unroll
        for (int n = 0; n < 4; ++n) {
            float a0 = acc[mt][n][0], a1 = acc[mt][n][1];
            float a2 = acc[mt][n][2], a3 = acc[mt][n][3];
            float t0 = __shfl_xor_sync(0xffffffffu, a0, 1);
            float t1 = __shfl_xor_sync(0xffffffffu, a1, 1);
            float t2 = __shfl_xor_sync(0xffffffffu, a2, 1);
            float t3 = __shfl_xor_sync(0xffffffffu, a3, 1);
            float gi = odd ? t2 : a0;
            float gf = odd ? t3 : a1;
            float gg = odd ? a2 : t0;
            float go = odd ? a3 : t1;
            float c = sigm(gf) * cs[mt][n] + sigm(gi) * tanh_(gg);
            cs[mt][n] = c;
            float h = sigm(go) * tanh_(c);
            hp[mt][n] = (uint32_t)f16u(h);
        }
    }
}

// ---------------- main persistent clustered kernel ----------------
__global__ void __launch_bounds__(NT, 1) __cluster_dims__(CLUSTER, 1, 1)
decoder_kernel(const float* __restrict__ z,
               const float* __restrict__ w_lh, const float* __restrict__ b_lh,
               const float* __restrict__ w_lc, const float* __restrict__ b_lc,
               const float* __restrict__ b_ih1, const float* __restrict__ b_hh1,
               const float* __restrict__ b_proj,
               float* __restrict__ out) {
    extern __shared__ __align__(16) char smem[];
    uint16_t* Ah  = (uint16_t*)smem;                 // [32][AS] fp16 activations (ping-pong)
    float*    pt  = (float*)(Ah + 32 * AS);          // [8][32][33] proj partials
    float*    z_s = pt + 8 * 32 * 33;                // [32][32]

    const int tid  = threadIdx.x;
    const int wid  = tid >> 5;
    const int lane = tid & 31;
    const int tig  = lane & 3;
    const int odd  = lane & 1;
    uint32_t cr;
    asm("mov.u32 %0, %%cluster_ctarank;" : "=r"(cr));
    const int slot = (int)cr * 16 + wid;             // 0..31 column-owner slot
    const int r0   = (blockIdx.x / CLUSTER) * ROWS;
    const int ubase  = slot * 8 + (tig >> 1);
    const int rbaseA = (lane >> 2) + (odd ? 8 : 0);
    const int myrow[2] = { rbaseA, 16 + rbaseA };
    const bool packlead = (lane & 2) == 0;

    // ---- stage z; init x-pad cols 0..31 (col 20 = fp16 1.0 bias column) ----
    for (int i = tid; i < ROWS * LATD; i += NT) z_s[i] = z[(size_t)r0 * LATD + i];
    for (int i = tid; i < 32 * 32; i += NT) {
        int r = i >> 5, c = i & 31;
        Ah[r * AS + c] = (c == 20) ? (uint16_t)0x3C00 : (uint16_t)0;
    }
    __syncthreads();

    // ---- c-state init in C-fragment layout (own units, both m-tiles) ----
    float c0st[2][4], c1st[2][4];
    #pragma unroll
    for (int mt = 0; mt < 2; ++mt)
        #pragma unroll
        for (int nt = 0; nt < 4; ++nt) {
            int u = ubase + nt * 2;
            float s0 = b_lc[u], s1 = b_lc[HID + u];
            for (int k = 0; k < LATD; ++k) {
                float wa = __ldg(w_lc + (size_t)u * LATD + k);
                float wb = __ldg(w_lc + (size_t)(HID + u) * LATD + k);
                float zv = z_s[myrow[mt] * LATD + k];
                s0 = fmaf(zv, wa, s0);  s1 = fmaf(zv, wb, s1);
            }
            c0st[mt][nt] = s0;  c1st[mt][nt] = s1;
        }

    // ---- layer1 gate biases, hoisted into registers (columns this warp owns) ----
    float bL1x[4], bL1y[4];
    #pragma unroll
    for (int nt = 0; nt < 4; ++nt) {
        int n0 = slot * 32 + nt * 8 + 2 * tig;
        int u0 = n0 >> 2, g0 = n0 & 3;
        int n1 = n0 + 1;
        int u1 = n1 >> 2, g1 = n1 & 3;
        bL1x[nt] = b_ih1[g0 * HID + u0] + b_hh1[g0 * HID + u0];
        bL1y[nt] = b_ih1[g1 * HID + u1] + b_hh1[g1 * HID + u1];
    }

    // ---- h-state init into buffer 0 (each CTA fills full A; init-only) ----
    {
        int u2 = tid & 255, rb = (tid >> 8) * 16;
        float h0v[16], h1v[16];
        #pragma unroll
        for (int r = 0; r < 16; ++r) { h0v[r] = b_lh[u2]; h1v[r] = b_lh[HID + u2]; }
        for (int k = 0; k < LATD; ++k) {
            float wa = __ldg(w_lh + (size_t)u2 * LATD + k);
            float wb = __ldg(w_lh + (size_t)(HID + u2) * LATD + k);
            #pragma unroll
            for (int r = 0; r < 16; ++r) {
                float zv = z_s[(rb + r) * LATD + k];
                h0v[r] = fmaf(zv, wa, h0v[r]);
                h1v[r] = fmaf(zv, wb, h1v[r]);
            }
        }
        #pragma unroll
        for (int r = 0; r < 16; ++r) {
            Ah[(rb + r) * AS + 32  + u2] = f16u(h0v[r]);   // h0 buffer 0 (col 32)
            Ah[(rb + r) * AS + 544 + u2] = f16u(h1v[r]);   // h1 buffer 0 (col 544)
        }
    }

    // ---- projection-reduce assignments (fixed across t) ----
    int pr_[2], pd_[2];
    float pb_[2];
    int pn = 0;
    for (int o = tid; o < ROWS * DIM; o += NT) {
        pr_[pn] = o / DIM;
        pd_[pn] = o - pr_[pn] * DIM;
        pb_[pn] = b_proj[pd_[pn]];
        ++pn;
    }
    __syncthreads();

    const uint32_t AhB = smem_u32(Ah);
    const uint32_t pAh = mapa_sh(AhB, cr ^ 1u);
    const uint32_t aH = AhB + (lane & 15) * ROWB + (lane >> 4) * 16;
    const uint4* wf0 = g_W0 + (size_t)slot * KS0 * 64 + lane;
    const uint4* wf1 = g_W1 + (size_t)slot * KS1 * 64 + lane;
    const int pk = wid >> 1;                         // proj K-slice 0..7
    const int pm = wid & 1;                          // proj m-tile
    const uint4* wfP = g_PJ + (size_t)pk * 128 + lane;

    cluster_sync_();

    // =============================== time loop ===============================
    for (int t = 0; t < TST; ++t) {
        const int rp = t & 1, wp = rp ^ 1;
        const uint32_t h0rB = (uint32_t)(32 + rp * 256) * 2;
        const uint32_t h0wB = (uint32_t)(32 + wp * 256) * 2;
        const uint32_t h1rB = (uint32_t)(544 + rp * 256) * 2;
        const uint32_t h1wB = (uint32_t)(544 + wp * 256) * 2;
        const int h0wC = 32 + wp * 256;
        const int h1wC = 544 + wp * 256;
        uint32_t hp[2][4];
        float acc[2][4][4];

        // ---- layer 0 : x (2 ks, bias col) + h0_old (16 ks) ----
        #pragma unroll
        for (int mt = 0; mt < 2; ++mt)
            #pragma unroll
            for (int n = 0; n < 4; ++n)
                #pragma unroll
                for (int i = 0; i < 4; ++i) acc[mt][n][i] = 0.f;
        mma_seg<2>(aH, wf0, acc);
        mma_seg<16>(aH + h0rB, wf0 + 2 * 64, acc);
        lstm_epi(acc, odd, c0st, hp);
        // store h0_new into write buffer (no pre-sync needed: distinct buffer)
        #pragma unroll
        for (int mt = 0; mt < 2; ++mt)
            #pragma unroll
            for (int nt = 0; nt < 4; ++nt) {
                uint32_t oth = __shfl_xor_sync(0xffffffffu, hp[mt][nt], 2);
                if (packlead) {
                    uint32_t v = (hp[mt][nt] & 0xffffu) | (oth << 16);
                    int row = myrow[mt], u = slot * 8 + nt * 2;
                    uint32_t off = (uint32_t)(row * AS + h0wC + u) * 2;
                    *reinterpret_cast<uint32_t*>(&Ah[row * AS + h0wC + u]) = v;
                    st_remote_u32(pAh + off, v);
                }
            }
        cluster_arrive_();                            // A1: my h0_new stores released

        // ---- layer 1 part A : h1_old half (independent of h0_new) ----
        #pragma unroll
        for (int mt = 0; mt < 2; ++mt)
            #pragma unroll
            for (int n = 0; n < 4; ++n) {
                acc[mt][n][0] = bL1x[n]; acc[mt][n][1] = bL1y[n];
                acc[mt][n][2] = bL1x[n]; acc[mt][n][3] = bL1y[n];
            }
        mma_seg<16>(aH + h1rB, wf1 + 16 * 64, acc);
        cluster_wait_();                              // W1: peer h0_new arrived (local too)

        // ---- layer 1 part B : h0_new half ----
        mma_seg<16>(aH + h0wB, wf1, acc);
        lstm_epi(acc, odd, c1st, hp);
        #pragma unroll
        for (int mt = 0; mt < 2; ++mt)
            #pragma unroll
            for (int nt = 0; nt < 4; ++nt) {
                uint32_t oth = __shfl_xor_sync(0xffffffffu, hp[mt][nt], 2);
                if (packlead) {
                    uint32_t v = (hp[mt][nt] & 0xffffu) | (oth << 16);
                    int row = myrow[mt], u = slot * 8 + nt * 2;
                    uint32_t off = (uint32_t)(row * AS + h1wC + u) * 2;
                    *reinterpret_cast<uint32_t*>(&Ah[row * AS + h1wC + u]) = v;
                    st_remote_u32(pAh + off, v);
                }
            }
        cluster_arrive_();                            // A2
        cluster_wait_();                              // W2: all h1_new visible

        // ---- projection MMA: 8 K-slices x 2 m-tiles across 16 warps ----
        {
            float pac[4][4];
            mma_proj(aH + pm * MTOFF + h1wB + pk * 64, wfP, pac);
            #pragma unroll
            for (int n = 0; n < 4; ++n) {
                int rr = pm * 16 + (lane >> 2);
                float* p = pt + pk * 1056 + rr * 33 + n * 8 + tig * 2;
                p[0]          = pac[n][0];
                p[1]          = pac[n][1];
                p[8 * 33]     = pac[n][2];
                p[8 * 33 + 1] = pac[n][3];
            }
        }
        __syncthreads();

        // ---- reduce partials + bias; rank writes its half of rows; feed back x ----
        for (int i2 = 0; i2 < pn; ++i2) {
            int r = pr_[i2], d = pd_[i2];
            float y = pb_[i2];
            #pragma unroll
            for (int w8 = 0; w8 < 8; ++w8) y += pt[w8 * 1056 + r * 33 + d];
            if ((uint32_t)(r >> 4) == cr)
                out[(size_t)(r0 + r) * (TST * DIM) + (size_t)t * DIM + d] = y;
            Ah[r * AS + d] = f16u(y);
        }
        __syncthreads();
    }
    cluster_sync_();
}

extern "C" void kernel_launch(void* const* d_in, const int* in_sizes, int n_in,
                              void* d_out, int out_size) {
    const int wbase = (n_in >= 17) ? 3 : 2;

    const float* z      = (const float*)d_in[0];
    const float* w_lh   = (const float*)d_in[wbase + 0];
    const float* b_lh   = (const float*)d_in[wbase + 1];
    const float* w_lc   = (const float*)d_in[wbase + 2];
    const float* b_lc   = (const float*)d_in[wbase + 3];
    const float* w_ih0  = (const float*)d_in[wbase + 4];
    const float* w_hh0  = (const float*)d_in[wbase + 5];
    const float* b_ih0  = (const float*)d_in[wbase + 6];
    const float* b_hh0  = (const float*)d_in[wbase + 7];
    const float* w_ih1  = (const float*)d_in[wbase + 8];
    const float* w_hh1  = (const float*)d_in[wbase + 9];
    const float* b_ih1  = (const float*)d_in[wbase + 10];
    const float* b_hh1  = (const float*)d_in[wbase + 11];
    const float* w_proj = (const float*)d_in[wbase + 12];
    const float* b_proj = (const float*)d_in[wbase + 13];

    static bool attr_set = false;
    if (!attr_set) {
        cudaFuncSetAttribute(decoder_kernel,
                             cudaFuncAttributeMaxDynamicSharedMemorySize, SMEM_BYTES);
        attr_set = true;
    }

    repack_kernel<<<512, 256>>>(w_ih0, w_hh0, b_ih0, b_hh0,
                                w_ih1, w_hh1, w_proj);
    decoder_kernel<<<NCTA, NT, SMEM_BYTES>>>(z, w_lh, b_lh, w_lc, b_lc,
                                             b_ih1, b_hh1,
                                             b_proj, (float*)d_out);
}

// round 16
// speedup vs baseline: 1.9792x; 1.0833x over previous
#include <cuda_runtime.h>
#include <cuda_fp16.h>
#include <cstdint>

#define BATCH   2048
#define LATD    32
#define HID     256
#define DIM     20
#define TST     512

#define ROWS    32                 // batch rows per CLUSTER
#define CLUSTER 2
#define NCTA    ((BATCH / ROWS) * CLUSTER)   // 128
#define NT      512                // 16 warps per CTA, each owns 32 gate columns
#define NSLOT   32                 // global column-owner slots (2 CTAs x 16)

#define KS0     18                 // layer0: x-pad (2 ks) + h0 (16 ks)
#define KS1     32                 // layer1: h0_new (16 ks) + h1_old (16 ks)
#define AS      1064               // u16 elements per activation row (ping-pong buffers)
#define ROWB    (AS * 2)           // 2128 bytes per row
#define MTOFF   (16 * ROWB)

// activation column bases (u16 units): x 0..31 (bias col 20), h0[p] 32+p*256, h1[p] 544+p*256
#define SMEM_BYTES (32*AS*2 + 8*32*33*4 + ROWS*LATD*4)   // 105984

// ---------------- fragment-major packed fp16 weights (repacked each launch) ----------------
__device__ uint4 g_W0[NSLOT * KS0 * 2 * 32];
__device__ uint4 g_W1[NSLOT * KS1 * 2 * 32];   // ks 0..15 = h0 cols, ks 16..31 = h1 cols
__device__ uint4 g_PJ[8 * 2 * 2 * 32];         // [pk][ks][pp][lane]

// ---------------- helpers ----------------
__device__ __forceinline__ float tanh_fast(float x) {
    float r; asm("tanh.approx.f32 %0, %1;" : "=f"(r) : "f"(x)); return r;
}
__device__ __forceinline__ float sigm(float x) {
    return fmaf(0.5f, tanh_fast(0.5f * x), 0.5f);
}
__device__ __forceinline__ unsigned short f16u(float x) {
    return __half_as_ushort(__float2half_rn(x));
}
__device__ __forceinline__ uint32_t f16x2(float a, float b) {
    return (uint32_t)f16u(a) | ((uint32_t)f16u(b) << 16);
}
__device__ __forceinline__ uint32_t smem_u32(const void* p) {
    uint32_t a;
    asm("{ .reg .u64 t; cvta.to.shared.u64 t, %1; cvt.u32.u64 %0, t; }" : "=r"(a) : "l"(p));
    return a;
}
__device__ __forceinline__ uint32_t mapa_sh(uint32_t addr, uint32_t rank) {
    uint32_t r;
    asm("mapa.shared::cluster.u32 %0, %1, %2;" : "=r"(r) : "r"(addr), "r"(rank));
    return r;
}
__device__ __forceinline__ void st_remote_u64(uint32_t addr, unsigned long long v) {
    asm volatile("st.shared::cluster.b64 [%0], %1;" :: "r"(addr), "l"(v) : "memory");
}
__device__ __forceinline__ void cluster_sync_() {
    asm volatile("barrier.cluster.arrive.aligned;" ::: "memory");
    asm volatile("barrier.cluster.wait.aligned;" ::: "memory");
}
__device__ __forceinline__ void cluster_arrive_() {
    asm volatile("barrier.cluster.arrive.aligned;" ::: "memory");
}
__device__ __forceinline__ void cluster_wait_() {
    asm volatile("barrier.cluster.wait.aligned;" ::: "memory");
}
__device__ __forceinline__ void prefetchL1(const void* p) {
    asm volatile("prefetch.global.L1 [%0];" :: "l"(p));
}
__device__ __forceinline__ void ldsm4(uint32_t& r0, uint32_t& r1, uint32_t& r2, uint32_t& r3,
                                      uint32_t a) {
    asm volatile("ldmatrix.sync.aligned.m8n8.x4.shared.b16 {%0,%1,%2,%3}, [%4];"
                 : "=r"(r0), "=r"(r1), "=r"(r2), "=r"(r3) : "r"(a));
}
__device__ __forceinline__ void mma16816(float* c, uint32_t a0, uint32_t a1, uint32_t a2,
                                         uint32_t a3, uint32_t b0, uint32_t b1) {
    asm volatile(
        "mma.sync.aligned.m16n8k16.row.col.f32.f16.f16.f32 "
        "{%0,%1,%2,%3}, {%4,%5,%6,%7}, {%8,%9}, {%0,%1,%2,%3};"
        : "+f"(c[0]), "+f"(c[1]), "+f"(c[2]), "+f"(c[3])
        : "r"(a0), "r"(a1), "r"(a2), "r"(a3), "r"(b0), "r"(b1));
}

// ---------------- repack: weight element accessors ----------------
__device__ __forceinline__ float W0val(int kc, int n,
                                       const float* w_ih0, const float* w_hh0,
                                       const float* b_ih0, const float* b_hh0) {
    int u = n >> 2, g = n & 3, row = g * HID + u;
    if (kc < DIM)  return w_ih0[row * DIM + kc];
    if (kc == 20)  return b_ih0[row] + b_hh0[row];
    if (kc < 32)   return 0.f;
    return w_hh0[row * HID + (kc - 32)];
}
__device__ __forceinline__ float W1val(int kc, int n,
                                       const float* w_ih1, const float* w_hh1) {
    int u = n >> 2, g = n & 3, row = g * HID + u;
    if (kc >= 288) return w_hh1[row * HID + (kc - 288)];
    return w_ih1[row * HID + (kc - 32)];
}

__global__ void repack_kernel(const float* __restrict__ w_ih0, const float* __restrict__ w_hh0,
                              const float* __restrict__ b_ih0, const float* __restrict__ b_hh0,
                              const float* __restrict__ w_ih1, const float* __restrict__ w_hh1,
                              const float* __restrict__ w_proj) {
    const int stride = gridDim.x * blockDim.x;
    const int base   = blockIdx.x * blockDim.x + threadIdx.x;

    const int N0 = NSLOT * KS0 * 2 * 32;
    for (int idx = base; idx < N0; idx += stride) {
        int lane = idx & 31, t = idx >> 5;
        int pp = t & 1; t >>= 1;
        int ks = t % KS0, s = t / KS0;
        int na = s * 32 + pp * 16 + (lane >> 2);
        int nb = na + 8;
        int kc = ks * 16 + (lane & 3) * 2;
        uint4 v;
        v.x = f16x2(W0val(kc,     na, w_ih0, w_hh0, b_ih0, b_hh0),
                    W0val(kc + 1, na, w_ih0, w_hh0, b_ih0, b_hh0));
        v.y = f16x2(W0val(kc + 8, na, w_ih0, w_hh0, b_ih0, b_hh0),
                    W0val(kc + 9, na, w_ih0, w_hh0, b_ih0, b_hh0));
        v.z = f16x2(W0val(kc,     nb, w_ih0, w_hh0, b_ih0, b_hh0),
                    W0val(kc + 1, nb, w_ih0, w_hh0, b_ih0, b_hh0));
        v.w = f16x2(W0val(kc + 8, nb, w_ih0, w_hh0, b_ih0, b_hh0),
                    W0val(kc + 9, nb, w_ih0, w_hh0, b_ih0, b_hh0));
        g_W0[idx] = v;
    }
    const int N1 = NSLOT * KS1 * 2 * 32;
    for (int idx = base; idx < N1; idx += stride) {
        int lane = idx & 31, t = idx >> 5;
        int pp = t & 1; t >>= 1;
        int ks = t % KS1, s = t / KS1;
        int na = s * 32 + pp * 16 + (lane >> 2);
        int nb = na + 8;
        int kc = 32 + ks * 16 + (lane & 3) * 2;
        uint4 v;
        v.x = f16x2(W1val(kc,     na, w_ih1, w_hh1), W1val(kc + 1, na, w_ih1, w_hh1));
        v.y = f16x2(W1val(kc + 8, na, w_ih1, w_hh1), W1val(kc + 9, na, w_ih1, w_hh1));
        v.z = f16x2(W1val(kc,     nb, w_ih1, w_hh1), W1val(kc + 1, nb, w_ih1, w_hh1));
        v.w = f16x2(W1val(kc + 8, nb, w_ih1, w_hh1), W1val(kc + 9, nb, w_ih1, w_hh1));
        g_W1[idx] = v;
    }
    const int NP = 8 * 2 * 2 * 32;
    for (int idx = base; idx < NP; idx += stride) {
        int lane = idx & 31, t = idx >> 5;
        int pp = t & 1; t >>= 1;
        int ks = t & 1; t >>= 1;
        int w  = t;                                   // 0..7 (proj K-slice)
        int na = pp * 16 + (lane >> 2);
        int nb = na + 8;
        int kc = w * 32 + ks * 16 + (lane & 3) * 2;
        auto PV = [&](int n, int k) -> float {
            return (n < DIM) ? w_proj[n * HID + k] : 0.f;
        };
        uint4 v;
        v.x = f16x2(PV(na, kc),     PV(na, kc + 1));
        v.y = f16x2(PV(na, kc + 8), PV(na, kc + 9));
        v.z = f16x2(PV(nb, kc),     PV(nb, kc + 1));
        v.w = f16x2(PV(nb, kc + 8), PV(nb, kc + 9));
        g_PJ[idx] = v;
    }
}

// ---------------- gate MMA segment: 4 n-tiles x 2 m-tiles, accumulating ----------------
template <int KSTEPS>
__device__ __forceinline__ void mma_seg(uint32_t aHi,
                                        const uint4* __restrict__ wf,
                                        float (&acc)[2][4][4]) {
    uint4 B0 = __ldg(wf), B1 = __ldg(wf + 32);
    #pragma unroll 2
    for (int ks = 0; ks < KSTEPS; ++ks) {
        if (ks + 2 < KSTEPS) {
            prefetchL1(wf + (size_t)(ks + 2) * 64);
            prefetchL1(wf + (size_t)(ks + 2) * 64 + 32);
        }
        uint4 B0n, B1n;
        if (ks + 1 < KSTEPS) {
            B0n = __ldg(wf + (size_t)(ks + 1) * 64);
            B1n = __ldg(wf + (size_t)(ks + 1) * 64 + 32);
        }
        uint32_t h0, h1, h2, h3, h4, h5, h6, h7;
        ldsm4(h0, h1, h2, h3, aHi + ks * 32);
        ldsm4(h4, h5, h6, h7, aHi + MTOFF + ks * 32);
        mma16816(acc[0][0], h0, h1, h2, h3, B0.x, B0.y);
        mma16816(acc[1][0], h4, h5, h6, h7, B0.x, B0.y);
        mma16816(acc[0][1], h0, h1, h2, h3, B0.z, B0.w);
        mma16816(acc[1][1], h4, h5, h6, h7, B0.z, B0.w);
        mma16816(acc[0][2], h0, h1, h2, h3, B1.x, B1.y);
        mma16816(acc[1][2], h4, h5, h6, h7, B1.x, B1.y);
        mma16816(acc[0][3], h0, h1, h2, h3, B1.z, B1.w);
        mma16816(acc[1][3], h4, h5, h6, h7, B1.z, B1.w);
        B0 = B0n;  B1 = B1n;
    }
}

// ---------------- projection MMA: single m-tile, 4 n-tiles, K=32 (2 ks) ----------------
__device__ __forceinline__ void mma_proj(uint32_t aHi,
                                         const uint4* __restrict__ wf,
                                         float (&acc)[4][4]) {
    #pragma unroll
    for (int n = 0; n < 4; ++n)
        #pragma unroll
        for (int i = 0; i < 4; ++i) acc[n][i] = 0.f;
    #pragma unroll
    for (int ks = 0; ks < 2; ++ks) {
        uint4 B0 = __ldg(wf + (size_t)ks * 64);
        uint4 B1 = __ldg(wf + (size_t)ks * 64 + 32);
        uint32_t h0, h1, h2, h3;
        ldsm4(h0, h1, h2, h3, aHi + ks * 32);
        mma16816(acc[0], h0, h1, h2, h3, B0.x, B0.y);
        mma16816(acc[1], h0, h1, h2, h3, B0.z, B0.w);
        mma16816(acc[2], h0, h1, h2, h3, B1.x, B1.y);
        mma16816(acc[3], h0, h1, h2, h3, B1.z, B1.w);
    }
}

// ---------------- LSTM epilogue: gate regroup via lane-pair shuffle ----------------
__device__ __forceinline__ void lstm_epi(float (&acc)[2][4][4], int odd,
                                         float (&cs)[2][4], uint32_t (&hp)[2][4]) {
    #pragma unroll
    for (int mt = 0; mt < 2; ++mt) {
        #pragma unroll
        for (int n = 0; n < 4; ++n) {
            float a0 = acc[mt][n][0], a1 = acc[mt][n][1];
            float a2 = acc[mt][n][2], a3 = acc[mt][n][3];
            float t0 = __shfl_xor_sync(0xffffffffu, a0, 1);
            float t1 = __shfl_xor_sync(0xffffffffu, a1, 1);
            float t2 = __shfl_xor_sync(0xffffffffu, a2, 1);
            float t3 = __shfl_xor_sync(0xffffffffu, a3, 1);
            float gi = odd ? t2 : a0;
            float gf = odd ? t3 : a1;
            float gg = odd ? a2 : t0;
            float go = odd ? a3 : t1;
            float c = sigm(gf) * cs[mt][n] + sigm(gi) * tanh_fast(gg);
            cs[mt][n] = c;
            float h = sigm(go) * tanh_fast(c);
            hp[mt][n] = (uint32_t)f16u(h);
        }
    }
}

// ---------------- packed h write-back: 1x STS.128 local + 2x b64 remote per m-tile ----------------
__device__ __forceinline__ void store_h(uint32_t (&hp)[2][4], int slot, const int* myrow,
                                        int colC, uint16_t* Ah, uint32_t pAh, bool packlead) {
    #pragma unroll
    for (int mt = 0; mt < 2; ++mt) {
        uint32_t pr[4];
        #pragma unroll
        for (int nt = 0; nt < 4; ++nt) {
            uint32_t oth = __shfl_xor_sync(0xffffffffu, hp[mt][nt], 2);
            pr[nt] = (hp[mt][nt] & 0xffffu) | (oth << 16);
        }
        if (packlead) {
            int row = myrow[mt], u = slot * 8;
            uint32_t off = (uint32_t)(row * AS + colC + u) * 2;     // 16B aligned
            *reinterpret_cast<uint4*>(&Ah[row * AS + colC + u]) =
                make_uint4(pr[0], pr[1], pr[2], pr[3]);
            st_remote_u64(pAh + off,     (unsigned long long)pr[0] |
                                         ((unsigned long long)pr[1] << 32));
            st_remote_u64(pAh + off + 8, (unsigned long long)pr[2] |
                                         ((unsigned long long)pr[3] << 32));
        }
    }
}

// ---------------- main persistent clustered kernel ----------------
__global__ void __launch_bounds__(NT, 1) __cluster_dims__(CLUSTER, 1, 1)
decoder_kernel(const float* __restrict__ z,
               const float* __restrict__ w_lh, const float* __restrict__ b_lh,
               const float* __restrict__ w_lc, const float* __restrict__ b_lc,
               const float* __restrict__ b_ih1, const float* __restrict__ b_hh1,
               const float* __restrict__ b_proj,
               float* __restrict__ out) {
    extern __shared__ __align__(16) char smem[];
    uint16_t* Ah  = (uint16_t*)smem;                 // [32][AS] fp16 activations (ping-pong)
    float*    pt  = (float*)(Ah + 32 * AS);          // [8][32][33] proj partials
    float*    z_s = pt + 8 * 32 * 33;                // [32][32]

    const int tid  = threadIdx.x;
    const int wid  = tid >> 5;
    const int lane = tid & 31;
    const int tig  = lane & 3;
    const int odd  = lane & 1;
    uint32_t cr;
    asm("mov.u32 %0, %%cluster_ctarank;" : "=r"(cr));
    const int slot = (int)cr * 16 + wid;             // 0..31 column-owner slot
    const int r0   = (blockIdx.x / CLUSTER) * ROWS;
    const int ubase  = slot * 8 + (tig >> 1);
    const int rbaseA = (lane >> 2) + (odd ? 8 : 0);
    const int myrow[2] = { rbaseA, 16 + rbaseA };
    const bool packlead = (lane & 2) == 0;

    // ---- stage z; init x-pad cols 0..31 (col 20 = fp16 1.0 bias column) ----
    for (int i = tid; i < ROWS * LATD; i += NT) z_s[i] = z[(size_t)r0 * LATD + i];
    for (int i = tid; i < 32 * 32; i += NT) {
        int r = i >> 5, c = i & 31;
        Ah[r * AS + c] = (c == 20) ? (uint16_t)0x3C00 : (uint16_t)0;
    }
    __syncthreads();

    // ---- c-state init in C-fragment layout (own units, both m-tiles) ----
    float c0st[2][4], c1st[2][4];
    #pragma unroll
    for (int mt = 0; mt < 2; ++mt)
        #pragma unroll
        for (int nt = 0; nt < 4; ++nt) {
            int u = ubase + nt * 2;
            float s0 = b_lc[u], s1 = b_lc[HID + u];
            for (int k = 0; k < LATD; ++k) {
                float wa = __ldg(w_lc + (size_t)u * LATD + k);
                float wb = __ldg(w_lc + (size_t)(HID + u) * LATD + k);
                float zv = z_s[myrow[mt] * LATD + k];
                s0 = fmaf(zv, wa, s0);  s1 = fmaf(zv, wb, s1);
            }
            c0st[mt][nt] = s0;  c1st[mt][nt] = s1;
        }

    // ---- layer1 gate biases, hoisted into registers ----
    float bL1x[4], bL1y[4];
    #pragma unroll
    for (int nt = 0; nt < 4; ++nt) {
        int n0 = slot * 32 + nt * 8 + 2 * tig;
        int u0 = n0 >> 2, g0 = n0 & 3;
        int n1 = n0 + 1;
        int u1 = n1 >> 2, g1 = n1 & 3;
        bL1x[nt] = b_ih1[g0 * HID + u0] + b_hh1[g0 * HID + u0];
        bL1y[nt] = b_ih1[g1 * HID + u1] + b_hh1[g1 * HID + u1];
    }

    // ---- h-state init into buffer 0 (each CTA fills full A; init-only) ----
    {
        int u2 = tid & 255, rb = (tid >> 8) * 16;
        float h0v[16], h1v[16];
        #pragma unroll
        for (int r = 0; r < 16; ++r) { h0v[r] = b_lh[u2]; h1v[r] = b_lh[HID + u2]; }
        for (int k = 0; k < LATD; ++k) {
            float wa = __ldg(w_lh + (size_t)u2 * LATD + k);
            float wb = __ldg(w_lh + (size_t)(HID + u2) * LATD + k);
            #pragma unroll
            for (int r = 0; r < 16; ++r) {
                float zv = z_s[(rb + r) * LATD + k];
                h0v[r] = fmaf(zv, wa, h0v[r]);
                h1v[r] = fmaf(zv, wb, h1v[r]);
            }
        }
        #pragma unroll
        for (int r = 0; r < 16; ++r) {
            Ah[(rb + r) * AS + 32  + u2] = f16u(h0v[r]);   // h0 buffer 0
            Ah[(rb + r) * AS + 544 + u2] = f16u(h1v[r]);   // h1 buffer 0
        }
    }

    // ---- projection-reduce assignments (fixed across t) ----
    int pr_[2], pd_[2];
    float pb_[2];
    int pn = 0;
    for (int o = tid; o < ROWS * DIM; o += NT) {
        pr_[pn] = o / DIM;
        pd_[pn] = o - pr_[pn] * DIM;
        pb_[pn] = b_proj[pd_[pn]];
        ++pn;
    }
    __syncthreads();

    const uint32_t AhB = smem_u32(Ah);
    const uint32_t pAh = mapa_sh(AhB, cr ^ 1u);
    const uint32_t aH = AhB + (lane & 15) * ROWB + (lane >> 4) * 16;
    const uint4* wf0 = g_W0 + (size_t)slot * KS0 * 64 + lane;
    const uint4* wf1 = g_W1 + (size_t)slot * KS1 * 64 + lane;
    const int pk = wid >> 1;                         // proj K-slice 0..7
    const int pm = wid & 1;                          // proj m-tile
    const bool ownhalf = ((pk >> 2) == (int)cr);     // proj slice reads own CTA's h1 half
    const uint4* wfP = g_PJ + (size_t)pk * 128 + lane;

    cluster_sync_();

    // =============================== time loop ===============================
    for (int t = 0; t < TST; ++t) {
        const int rp = t & 1, wp = rp ^ 1;
        const uint32_t h0rB = (uint32_t)(32 + rp * 256) * 2;
        const uint32_t h0wB = (uint32_t)(32 + wp * 256) * 2;
        const uint32_t h1rB = (uint32_t)(544 + rp * 256) * 2;
        const uint32_t h1wB = (uint32_t)(544 + wp * 256) * 2;
        const int h0wC = 32 + wp * 256;
        const int h1wC = 544 + wp * 256;
        uint32_t hp[2][4];
        float acc[2][4][4];

        // ---- layer 0 : x (2 ks, bias col) + h0_old (16 ks) ----
        #pragma unroll
        for (int mt = 0; mt < 2; ++mt)
            #pragma unroll
            for (int n = 0; n < 4; ++n)
                #pragma unroll
                for (int i = 0; i < 4; ++i) acc[mt][n][i] = 0.f;
        mma_seg<2>(aH, wf0, acc);
        mma_seg<16>(aH + h0rB, wf0 + 2 * 64, acc);
        lstm_epi(acc, odd, c0st, hp);
        store_h(hp, slot, myrow, h0wC, Ah, pAh, packlead);
        cluster_arrive_();                            // A1: my h0_new stores released

        // ---- layer 1 part A : h1_old half (independent of h0_new) ----
        #pragma unroll
        for (int mt = 0; mt < 2; ++mt)
            #pragma unroll
            for (int n = 0; n < 4; ++n) {
                acc[mt][n][0] = bL1x[n]; acc[mt][n][1] = bL1y[n];
                acc[mt][n][2] = bL1x[n]; acc[mt][n][3] = bL1y[n];
            }
        mma_seg<16>(aH + h1rB, wf1 + 16 * 64, acc);
        cluster_wait_();                              // W1: peer h0_new arrived

        // ---- layer 1 part B : h0_new half ----
        mma_seg<16>(aH + h0wB, wf1, acc);
        lstm_epi(acc, odd, c1st, hp);
        store_h(hp, slot, myrow, h1wC, Ah, pAh, packlead);
        cluster_arrive_();                            // A2
        __syncthreads();                              // local h1_new visible CTA-wide

        // ---- projection: own-half slices run BEFORE the cluster wait ----
        float pac[4][4];
        if (ownhalf) mma_proj(aH + pm * MTOFF + h1wB + pk * 64, wfP, pac);
        cluster_wait_();                              // W2: peer h1_new visible
        if (!ownhalf) mma_proj(aH + pm * MTOFF + h1wB + pk * 64, wfP, pac);
        {
            #pragma unroll
            for (int n = 0; n < 4; ++n) {
                int rr = pm * 16 + (lane >> 2);
                float* p = pt + pk * 1056 + rr * 33 + n * 8 + tig * 2;
                p[0]          = pac[n][0];
                p[1]          = pac[n][1];
                p[8 * 33]     = pac[n][2];
                p[8 * 33 + 1] = pac[n][3];
            }
        }
        __syncthreads();

        // ---- reduce partials + bias; rank writes its half of rows; feed back x ----
        for (int i2 = 0; i2 < pn; ++i2) {
            int r = pr_[i2], d = pd_[i2];
            float y = pb_[i2];
            #pragma unroll
            for (int w8 = 0; w8 < 8; ++w8) y += pt[w8 * 1056 + r * 33 + d];
            if ((uint32_t)(r >> 4) == cr)
                out[(size_t)(r0 + r) * (TST * DIM) + (size_t)t * DIM + d] = y;
            Ah[r * AS + d] = f16u(y);
        }
        __syncthreads();
    }
    cluster_sync_();
}

extern "C" void kernel_launch(void* const* d_in, const int* in_sizes, int n_in,
                              void* d_out, int out_size) {
    const int wbase = (n_in >= 17) ? 3 : 2;

    const float* z      = (const float*)d_in[0];
    const float* w_lh   = (const float*)d_in[wbase + 0];
    const float* b_lh   = (const float*)d_in[wbase + 1];
    const float* w_lc   = (const float*)d_in[wbase + 2];
    const float* b_lc   = (const float*)d_in[wbase + 3];
    const float* w_ih0  = (const float*)d_in[wbase + 4];
    const float* w_hh0  = (const float*)d_in[wbase + 5];
    const float* b_ih0  = (const float*)d_in[wbase + 6];
    const float* b_hh0  = (const float*)d_in[wbase + 7];
    const float* w_ih1  = (const float*)d_in[wbase + 8];
    const float* w_hh1  = (const float*)d_in[wbase + 9];
    const float* b_ih1  = (const float*)d_in[wbase + 10];
    const float* b_hh1  = (const float*)d_in[wbase + 11];
    const float* w_proj = (const float*)d_in[wbase + 12];
    const float* b_proj = (const float*)d_in[wbase + 13];

    static bool attr_set = false;
    if (!attr_set) {
        cudaFuncSetAttribute(decoder_kernel,
                             cudaFuncAttributeMaxDynamicSharedMemorySize, SMEM_BYTES);
        attr_set = true;
    }

    repack_kernel<<<512, 256>>>(w_ih0, w_hh0, b_ih0, b_hh0,
                                w_ih1, w_hh1, w_proj);
    decoder_kernel<<<NCTA, NT, SMEM_BYTES>>>(z, w_lh, b_lh, w_lc, b_lc,
                                             b_ih1, b_hh1,
                                             b_proj, (float*)d_out);
}